// round 7
// baseline (speedup 1.0000x reference)
#include <cuda_runtime.h>
#include <mma.h>
#include <cstdint>

using namespace nvcuda;

#define BM 128
#define BN 128
#define BK 32
#define APAD 4
#define NWARPS 8

// ---- scratch (__device__ globals; no allocations allowed) ----
__device__ float g_P[8u * 256u * 4096u];   // phi  conv out, viewed [512,2048]/batch
__device__ float g_T[8u * 256u * 4096u];   // theta conv out
__device__ float g_G[8u * 256u * 4096u];   // g    conv out
__device__ float g_S[8u * 2048u * 2048u];  // S^T then normalized attn E
__device__ float g_O[8u * 256u * 4096u];   // out_nl, viewed [256,4096]/batch

// ============================================================================
// Tiled TF32 wmma GEMM: C[b] = A[b] @ B[b] (+ bias[row]) (+ addend[b])
//   A: TRANS_A ? [K,M] row-major (lda=M)  :  [M,K] row-major (lda=K)
//   B: [K,N] row-major
//   EPI: 0 = plain store, 1 = +bias[gm], 2 = +bias[gm] + addend[b][gm][gn]
// M % 128 == 0, N % 128 == 0, K % 32 == 0 (true for all calls here)
// ============================================================================
template <bool TRANS_A, int EPI>
__global__ __launch_bounds__(256, 2)
void gemm_tf32_kernel(const float* __restrict__ A, const float* __restrict__ B,
                      float* __restrict__ C, const float* __restrict__ bias,
                      const float* __restrict__ addend,
                      int M, int N, int K,
                      long long sA, long long sB, long long sC, long long sAdd)
{
    __shared__ __align__(16) float As[BK][BM + APAD];  // As[k][m] (col-major A tile)
    __shared__ __align__(16) float Bs[BK][BN + APAD];  // Bs[k][n]
    __shared__ __align__(16) float epi[NWARPS][256];

    const int bn0 = blockIdx.x * BN;
    const int bm0 = blockIdx.y * BM;
    const int batch = blockIdx.z;

    const float* Ab = A + (long long)batch * sA;
    const float* Bb = B + (long long)batch * sB;
    float* Cb = C + (long long)batch * sC;

    const int tid = threadIdx.x;
    const int warpId = tid >> 5;
    const int lane = tid & 31;
    const int wm = warpId >> 2;  // 0..1  (64-row warp tile)
    const int wn = warpId & 3;   // 0..3  (32-col warp tile)

    wmma::fragment<wmma::accumulator, 16, 16, 8, float> acc[4][2];
#pragma unroll
    for (int i = 0; i < 4; i++)
#pragma unroll
        for (int j = 0; j < 2; j++) wmma::fill_fragment(acc[i][j], 0.0f);

    for (int k0 = 0; k0 < K; k0 += BK) {
        // ---- stage A tile into As[k][m] (tf32-rounded) ----
        if (TRANS_A) {
            const int lda = M;
#pragma unroll
            for (int it = 0; it < 4; it++) {
                int slot = tid + it * 256;      // 0..1023 float4 slots of 32x128
                int k  = slot >> 5;             // 0..31
                int c4 = slot & 31;             // 0..31
                float4 v = *reinterpret_cast<const float4*>(
                    Ab + (long long)(k0 + k) * lda + bm0 + c4 * 4);
                v.x = wmma::__float_to_tf32(v.x);
                v.y = wmma::__float_to_tf32(v.y);
                v.z = wmma::__float_to_tf32(v.z);
                v.w = wmma::__float_to_tf32(v.w);
                *reinterpret_cast<float4*>(&As[k][c4 * 4]) = v;
            }
        } else {
            const int lda = K;
#pragma unroll
            for (int it = 0; it < 4; it++) {
                int slot = tid + it * 256;      // 0..1023 float4 slots of 128x8
                int m  = slot >> 3;             // 0..127
                int c4 = slot & 7;              // 0..7
                float4 v = *reinterpret_cast<const float4*>(
                    Ab + (long long)(bm0 + m) * lda + k0 + c4 * 4);
                As[c4 * 4 + 0][m] = wmma::__float_to_tf32(v.x);
                As[c4 * 4 + 1][m] = wmma::__float_to_tf32(v.y);
                As[c4 * 4 + 2][m] = wmma::__float_to_tf32(v.z);
                As[c4 * 4 + 3][m] = wmma::__float_to_tf32(v.w);
            }
        }
        // ---- stage B tile into Bs[k][n] ----
#pragma unroll
        for (int it = 0; it < 4; it++) {
            int slot = tid + it * 256;
            int k  = slot >> 5;
            int c4 = slot & 31;
            float4 v = *reinterpret_cast<const float4*>(
                Bb + (long long)(k0 + k) * N + bn0 + c4 * 4);
            v.x = wmma::__float_to_tf32(v.x);
            v.y = wmma::__float_to_tf32(v.y);
            v.z = wmma::__float_to_tf32(v.z);
            v.w = wmma::__float_to_tf32(v.w);
            *reinterpret_cast<float4*>(&Bs[k][c4 * 4]) = v;
        }
        __syncthreads();

#pragma unroll
        for (int kk = 0; kk < BK; kk += 8) {
            wmma::fragment<wmma::matrix_a, 16, 16, 8, wmma::precision::tf32,
                           wmma::col_major> af[4];
            wmma::fragment<wmma::matrix_b, 16, 16, 8, wmma::precision::tf32,
                           wmma::row_major> bf[2];
#pragma unroll
            for (int i = 0; i < 4; i++)
                wmma::load_matrix_sync(af[i], &As[kk][wm * 64 + i * 16], BM + APAD);
#pragma unroll
            for (int j = 0; j < 2; j++)
                wmma::load_matrix_sync(bf[j], &Bs[kk][wn * 32 + j * 16], BN + APAD);
#pragma unroll
            for (int i = 0; i < 4; i++)
#pragma unroll
                for (int j = 0; j < 2; j++)
                    wmma::mma_sync(acc[i][j], af[i], bf[j], acc[i][j]);
        }
        __syncthreads();
    }

    // ---- epilogue ----
    if (EPI == 0) {
#pragma unroll
        for (int i = 0; i < 4; i++)
#pragma unroll
            for (int j = 0; j < 2; j++) {
                int gm = bm0 + wm * 64 + i * 16;
                int gn = bn0 + wn * 32 + j * 16;
                wmma::store_matrix_sync(Cb + (long long)gm * N + gn, acc[i][j], N,
                                        wmma::mem_row_major);
            }
    } else {
#pragma unroll
        for (int i = 0; i < 4; i++)
#pragma unroll
            for (int j = 0; j < 2; j++) {
                wmma::store_matrix_sync(&epi[warpId][0], acc[i][j], 16,
                                        wmma::mem_row_major);
                __syncwarp();
#pragma unroll
                for (int e = 0; e < 8; e++) {
                    int idx = lane * 8 + e;  // 0..255 within the 16x16 tile
                    int r = idx >> 4, cl = idx & 15;
                    int gm = bm0 + wm * 64 + i * 16 + r;
                    int gn = bn0 + wn * 32 + j * 16 + cl;
                    float v = epi[warpId][idx] + bias[gm];
                    if (EPI == 2)
                        v += addend[(long long)batch * sAdd + (long long)gm * N + gn];
                    Cb[(long long)gm * N + gn] = v;
                }
                __syncwarp();
            }
    }
}

// ============================================================================
// Row softmax over S^T rows (length 2048). One block of 256 threads per row.
// Writes exp(v - max)/sum in place (i.e., fully normalized attn).
// ============================================================================
__global__ void softmax_rows_kernel(float* __restrict__ S)
{
    float* row = S + (size_t)blockIdx.x * 2048u;
    const int tid = threadIdx.x, lane = tid & 31, warp = tid >> 5;

    float4 a = reinterpret_cast<float4*>(row)[tid];
    float4 b = reinterpret_cast<float4*>(row)[tid + 256];

    float m = fmaxf(fmaxf(fmaxf(a.x, a.y), fmaxf(a.z, a.w)),
                    fmaxf(fmaxf(b.x, b.y), fmaxf(b.z, b.w)));
#pragma unroll
    for (int o = 16; o > 0; o >>= 1) m = fmaxf(m, __shfl_xor_sync(0xffffffffu, m, o));

    __shared__ float red[8];
    if (lane == 0) red[warp] = m;
    __syncthreads();
    float rm = red[0];
#pragma unroll
    for (int i = 1; i < 8; i++) rm = fmaxf(rm, red[i]);
    __syncthreads();

    a.x = __expf(a.x - rm); a.y = __expf(a.y - rm);
    a.z = __expf(a.z - rm); a.w = __expf(a.w - rm);
    b.x = __expf(b.x - rm); b.y = __expf(b.y - rm);
    b.z = __expf(b.z - rm); b.w = __expf(b.w - rm);

    float s = a.x + a.y + a.z + a.w + b.x + b.y + b.z + b.w;
#pragma unroll
    for (int o = 16; o > 0; o >>= 1) s += __shfl_xor_sync(0xffffffffu, s, o);
    if (lane == 0) red[warp] = s;
    __syncthreads();
    float rs = red[0];
#pragma unroll
    for (int i = 1; i < 8; i++) rs += red[i];

    float inv = 1.0f / rs;
    a.x *= inv; a.y *= inv; a.z *= inv; a.w *= inv;
    b.x *= inv; b.y *= inv; b.z *= inv; b.w *= inv;

    reinterpret_cast<float4*>(row)[tid]       = a;
    reinterpret_cast<float4*>(row)[tid + 256] = b;
}

// ============================================================================
extern "C" void kernel_launch(void* const* d_in, const int* in_sizes, int n_in,
                              void* d_out, int out_size)
{
    const float* x       = (const float*)d_in[0];
    const float* y       = (const float*)d_in[1];
    const float* w_phi   = (const float*)d_in[2];
    const float* b_phi   = (const float*)d_in[3];
    const float* w_theta = (const float*)d_in[4];
    const float* b_theta = (const float*)d_in[5];
    const float* w_g     = (const float*)d_in[6];
    const float* b_g     = (const float*)d_in[7];
    const float* w_mask  = (const float*)d_in[8];
    const float* b_mask  = (const float*)d_in[9];
    float* out = (float*)d_out;

    float *P, *T, *G, *S, *O;
    cudaGetSymbolAddress((void**)&P, g_P);
    cudaGetSymbolAddress((void**)&T, g_T);
    cudaGetSymbolAddress((void**)&G, g_G);
    cudaGetSymbolAddress((void**)&S, g_S);
    cudaGetSymbolAddress((void**)&O, g_O);

    const dim3 blk(256);
    const long long sImg  = 512LL * 4096;   // x/y per-batch stride
    const long long sHalf = 256LL * 4096;   // conv-out per-batch stride (== 512*2048)
    const long long sS    = 2048LL * 2048;  // scores per-batch stride

    // 1) conv1x1's: [256,512] x [512,4096] (+bias per row)
    gemm_tf32_kernel<false, 1><<<dim3(32, 2, 8), blk>>>(
        w_phi, y, P, b_phi, nullptr, 256, 4096, 512, 0, sImg, sHalf, 0);
    gemm_tf32_kernel<false, 1><<<dim3(32, 2, 8), blk>>>(
        w_theta, x, T, b_theta, nullptr, 256, 4096, 512, 0, sImg, sHalf, 0);
    gemm_tf32_kernel<false, 1><<<dim3(32, 2, 8), blk>>>(
        w_g, x, G, b_g, nullptr, 256, 4096, 512, 0, sImg, sHalf, 0);

    // 2) S^T[m,n] = sum_c phi_v[c,m] * theta_v[c,n]   (A transposed: [K=512, M=2048])
    gemm_tf32_kernel<true, 0><<<dim3(16, 16, 8), blk>>>(
        P, T, S, nullptr, nullptr, 2048, 2048, 512, sHalf, sHalf, sS, 0);

    // 3) row softmax over n (== reference softmax over axis 1), normalized in place
    softmax_rows_kernel<<<8 * 2048, 256>>>(S);

    // 4) Out_v[c,n] = sum_m g_v[c,m] * E[m,n]   ([512,2048] x [2048,2048])
    gemm_tf32_kernel<false, 0><<<dim3(16, 4, 8), blk>>>(
        G, S, O, nullptr, nullptr, 512, 2048, 2048, sHalf, sS, sHalf, 0);

    // 5) out = w_mask @ Out(view [256,4096]) + b_mask + x
    gemm_tf32_kernel<false, 2><<<dim3(32, 4, 8), blk>>>(
        w_mask, O, out, b_mask, x, 512, 4096, 256, 0, sHalf, sImg, sImg);
}

// round 10
// speedup vs baseline: 1.3373x; 1.3373x over previous
#include <cuda_runtime.h>
#include <cuda_bf16.h>
#include <mma.h>
#include <cstdint>
#include <type_traits>

using namespace nvcuda;

// ---- scratch (__device__ globals; no allocations allowed) ----
__device__ __align__(16) float         g_P[8u * 256u * 4096u];   // phi  conv out fp32 (viewed [512,2048]/b)
__device__ __align__(16) float         g_T[8u * 256u * 4096u];   // theta conv out fp32
__device__ __align__(16) float         g_S[8u * 2048u * 2048u];  // S^T fp32 scores
__device__ __align__(16) __nv_bfloat16 g_Gb[8u * 256u * 4096u];  // g conv out bf16 (viewed [512,2048]/b)
__device__ __align__(16) __nv_bfloat16 g_Eb[8u * 2048u * 2048u]; // normalized attn bf16
__device__ __align__(16) __nv_bfloat16 g_Ob[8u * 256u * 4096u];  // O-GEMM out bf16 (viewed [256,4096]/b)
__device__ __align__(16) __nv_bfloat16 g_Wm[512u * 256u];        // w_mask bf16

// ---- helpers ----
static __device__ __forceinline__ uint32_t s2u(const void* p) {
    uint32_t a;
    asm("{ .reg .u64 t; cvta.to.shared.u64 t, %1; cvt.u32.u64 %0, t; }" : "=r"(a) : "l"(p));
    return a;
}
static __device__ __forceinline__ void cpa16(uint32_t s, const void* g) {
    asm volatile("cp.async.cg.shared.global [%0], [%1], 16;" :: "r"(s), "l"(g));
}
static __device__ __forceinline__ void cpa_commit() {
    asm volatile("cp.async.commit_group;" ::: "memory");
}
template <int N>
static __device__ __forceinline__ void cpa_wait() {
    asm volatile("cp.async.wait_group %0;" :: "n"(N) : "memory");
}

template <typename T> struct WT;
template <> struct WT<float> {
    static constexpr int KW = 8;
    using AT = wmma::precision::tf32;
};
template <> struct WT<__nv_bfloat16> {
    static constexpr int KW = 16;
    using AT = __nv_bfloat16;
};

// ============================================================================
// Double-buffered cp.async GEMM, 128x128 CTA tile, 256 threads, warp tile 64x32.
//   T = float  -> tf32 mma (k=8 steps),  chunk CK=32
//   T = bf16   -> bf16 mma (k=16 steps), chunk CK=64
//   A: TRANS_A ? [K,M] (lda=M) : [M,K] (lda=K);  B: [K,N]
//   EPI: 0 fp32 plain | 1 fp32 +bias[gm] | 2 fp32 +bias[gm]+addend
//        3 bf16 +bias[gm] | 4 bf16 plain
// ============================================================================
template <typename T, bool TRANS_A, int EPI>
__global__ __launch_bounds__(256, 2)
void tc_gemm(const void* __restrict__ Ag, const void* __restrict__ Bg,
             void* __restrict__ Cg, const float* __restrict__ bias,
             const float* __restrict__ addend, int M, int N, int K,
             long long sA, long long sB, long long sC, long long sAdd)
{
    constexpr int CK  = 128 / (int)sizeof(T);
    constexpr int PAD = 16 / (int)sizeof(T);
    constexpr int EPR = 16 / (int)sizeof(T);
    constexpr int LDA = TRANS_A ? (128 + PAD) : (CK + PAD);
    constexpr int LDB = 128 + PAD;
    constexpr int ASZ = (TRANS_A ? CK * (128 + PAD) : 128 * (CK + PAD)) * (int)sizeof(T);
    constexpr int BSZ = CK * (128 + PAD) * (int)sizeof(T);
    using AMaj = typename std::conditional<TRANS_A, wmma::col_major, wmma::row_major>::type;

    extern __shared__ __align__(16) char sm[];

    const int tid = threadIdx.x, warpId = tid >> 5, lane = tid & 31;
    const int wm = warpId >> 2, wn = warpId & 3;
    const int bn0 = blockIdx.x * 128, bm0 = blockIdx.y * 128, batch = blockIdx.z;
    const T* Ab = (const T*)Ag + (long long)batch * sA;
    const T* Bb = (const T*)Bg + (long long)batch * sB;

    wmma::fragment<wmma::accumulator, 16, 16, WT<T>::KW, float> acc[4][2];
#pragma unroll
    for (int i = 0; i < 4; i++)
#pragma unroll
        for (int j = 0; j < 2; j++) wmma::fill_fragment(acc[i][j], 0.0f);

    auto stage = [&](int k0, int buf) {
        char* At = buf ? sm + ASZ : sm;
        char* Bt = buf ? sm + 2 * ASZ + BSZ : sm + 2 * ASZ;
        if (TRANS_A) {
            constexpr int CPR = 128 / EPR;
#pragma unroll
            for (int u = 0; u < CK * CPR / 256; u++) {
                int s = tid + u * 256;
                int r = s / CPR, c = s % CPR;
                cpa16(s2u(At + (r * LDA + c * EPR) * sizeof(T)),
                      Ab + (long long)(k0 + r) * M + bm0 + c * EPR);
            }
        } else {
            constexpr int CPR = CK / EPR;  // 8
#pragma unroll
            for (int u = 0; u < 128 * CPR / 256; u++) {
                int s = tid + u * 256;
                int r = s / CPR, c = s % CPR;
                cpa16(s2u(At + (r * LDA + c * EPR) * sizeof(T)),
                      Ab + (long long)(bm0 + r) * K + k0 + c * EPR);
            }
        }
        {
            constexpr int CPR = 128 / EPR;
#pragma unroll
            for (int u = 0; u < CK * CPR / 256; u++) {
                int s = tid + u * 256;
                int r = s / CPR, c = s % CPR;
                cpa16(s2u(Bt + (r * LDB + c * EPR) * sizeof(T)),
                      Bb + (long long)(k0 + r) * N + bn0 + c * EPR);
            }
        }
        cpa_commit();
    };

    const int NC = K / CK;
    stage(0, 0);
    for (int i = 0; i < NC; i++) {
        if (i + 1 < NC) {
            stage((i + 1) * CK, (i + 1) & 1);
            cpa_wait<1>();
        } else {
            cpa_wait<0>();
        }
        __syncthreads();

        const T* As = (const T*)((i & 1) ? sm + ASZ : sm);
        const T* Bs = (const T*)((i & 1) ? sm + 2 * ASZ + BSZ : sm + 2 * ASZ);
#pragma unroll
        for (int kk = 0; kk < CK; kk += WT<T>::KW) {
            wmma::fragment<wmma::matrix_a, 16, 16, WT<T>::KW, typename WT<T>::AT, AMaj> af[4];
            wmma::fragment<wmma::matrix_b, 16, 16, WT<T>::KW, typename WT<T>::AT,
                           wmma::row_major> bf[2];
#pragma unroll
            for (int i2 = 0; i2 < 4; i2++) {
                const T* p = TRANS_A ? &As[kk * LDA + wm * 64 + i2 * 16]
                                     : &As[(wm * 64 + i2 * 16) * LDA + kk];
                wmma::load_matrix_sync(af[i2], p, LDA);
            }
#pragma unroll
            for (int j = 0; j < 2; j++)
                wmma::load_matrix_sync(bf[j], &Bs[kk * LDB + wn * 32 + j * 16], LDB);
#pragma unroll
            for (int i2 = 0; i2 < 4; i2++)
#pragma unroll
                for (int j = 0; j < 2; j++)
                    wmma::mma_sync(acc[i2][j], af[i2], bf[j], acc[i2][j]);
        }
        __syncthreads();
    }

    // ---- epilogue ----
    if (EPI == 0) {
        float* Cb = (float*)Cg + (long long)batch * sC;
#pragma unroll
        for (int i = 0; i < 4; i++)
#pragma unroll
            for (int j = 0; j < 2; j++)
                wmma::store_matrix_sync(
                    Cb + (long long)(bm0 + wm * 64 + i * 16) * N + bn0 + wn * 32 + j * 16,
                    acc[i][j], N, wmma::mem_row_major);
    } else {
        float* epi = (float*)sm + warpId * 256;  // smem reused after mainloop
#pragma unroll
        for (int i = 0; i < 4; i++)
#pragma unroll
            for (int j = 0; j < 2; j++) {
                wmma::store_matrix_sync(epi, acc[i][j], 16, wmma::mem_row_major);
                __syncwarp();
#pragma unroll
                for (int e = 0; e < 8; e++) {
                    int idx = lane * 8 + e;
                    int r = idx >> 4, cl = idx & 15;
                    int gm = bm0 + wm * 64 + i * 16 + r;
                    int gn = bn0 + wn * 32 + j * 16 + cl;
                    float v = epi[idx];
                    if (EPI == 1 || EPI == 2 || EPI == 3) v += bias[gm];
                    if (EPI == 2)
                        v += addend[(long long)batch * sAdd + (long long)gm * N + gn];
                    if (EPI == 3 || EPI == 4)
                        ((__nv_bfloat16*)Cg + (long long)batch * sC)[(long long)gm * N + gn] =
                            __float2bfloat16(v);
                    else
                        ((float*)Cg + (long long)batch * sC)[(long long)gm * N + gn] = v;
                }
                __syncwarp();
            }
    }
}

// ============================================================================
// Row softmax over S^T rows (2048 fp32) -> normalized bf16 attn.
// ============================================================================
__global__ void softmax_rows_kernel(const float* __restrict__ S,
                                    __nv_bfloat16* __restrict__ E)
{
    const float* row = S + (size_t)blockIdx.x * 2048u;
    __nv_bfloat16* er = E + (size_t)blockIdx.x * 2048u;
    const int tid = threadIdx.x, lane = tid & 31, warp = tid >> 5;

    float4 a = reinterpret_cast<const float4*>(row)[tid];
    float4 b = reinterpret_cast<const float4*>(row)[tid + 256];

    float m = fmaxf(fmaxf(fmaxf(a.x, a.y), fmaxf(a.z, a.w)),
                    fmaxf(fmaxf(b.x, b.y), fmaxf(b.z, b.w)));
#pragma unroll
    for (int o = 16; o > 0; o >>= 1) m = fmaxf(m, __shfl_xor_sync(0xffffffffu, m, o));

    __shared__ float red[8];
    if (lane == 0) red[warp] = m;
    __syncthreads();
    float rm = red[0];
#pragma unroll
    for (int i = 1; i < 8; i++) rm = fmaxf(rm, red[i]);
    __syncthreads();

    a.x = __expf(a.x - rm); a.y = __expf(a.y - rm);
    a.z = __expf(a.z - rm); a.w = __expf(a.w - rm);
    b.x = __expf(b.x - rm); b.y = __expf(b.y - rm);
    b.z = __expf(b.z - rm); b.w = __expf(b.w - rm);

    float s = a.x + a.y + a.z + a.w + b.x + b.y + b.z + b.w;
#pragma unroll
    for (int o = 16; o > 0; o >>= 1) s += __shfl_xor_sync(0xffffffffu, s, o);
    if (lane == 0) red[warp] = s;
    __syncthreads();
    float rs = red[0];
#pragma unroll
    for (int i = 1; i < 8; i++) rs += red[i];

    float inv = 1.0f / rs;
    __nv_bfloat162 h0 = __floats2bfloat162_rn(a.x * inv, a.y * inv);
    __nv_bfloat162 h1 = __floats2bfloat162_rn(a.z * inv, a.w * inv);
    __nv_bfloat162 h2 = __floats2bfloat162_rn(b.x * inv, b.y * inv);
    __nv_bfloat162 h3 = __floats2bfloat162_rn(b.z * inv, b.w * inv);
    uint2 o0 = make_uint2(*(uint32_t*)&h0, *(uint32_t*)&h1);
    uint2 o1 = make_uint2(*(uint32_t*)&h2, *(uint32_t*)&h3);
    reinterpret_cast<uint2*>(er)[tid]       = o0;
    reinterpret_cast<uint2*>(er)[tid + 256] = o1;
}

// fp32 -> bf16 pack (for w_mask)
__global__ void f2bf_kernel(const float* __restrict__ in,
                            __nv_bfloat16* __restrict__ out, int n4)
{
    int i = blockIdx.x * blockDim.x + threadIdx.x;
    if (i < n4) {
        float4 v = reinterpret_cast<const float4*>(in)[i];
        __nv_bfloat162 h0 = __floats2bfloat162_rn(v.x, v.y);
        __nv_bfloat162 h1 = __floats2bfloat162_rn(v.z, v.w);
        reinterpret_cast<uint2*>(out)[i] = make_uint2(*(uint32_t*)&h0, *(uint32_t*)&h1);
    }
}

// ============================================================================
static constexpr int smem_for(int szT, bool trans)
{
    int CK = 128 / szT, PAD = 16 / szT;
    int A = (trans ? CK * (128 + PAD) : 128 * (CK + PAD)) * szT;
    int B = CK * (128 + PAD) * szT;
    return 2 * (A + B);
}

extern "C" void kernel_launch(void* const* d_in, const int* in_sizes, int n_in,
                              void* d_out, int out_size)
{
    const float* x       = (const float*)d_in[0];
    const float* y       = (const float*)d_in[1];
    const float* w_phi   = (const float*)d_in[2];
    const float* b_phi   = (const float*)d_in[3];
    const float* w_theta = (const float*)d_in[4];
    const float* b_theta = (const float*)d_in[5];
    const float* w_g     = (const float*)d_in[6];
    const float* b_g     = (const float*)d_in[7];
    const float* w_mask  = (const float*)d_in[8];
    const float* b_mask  = (const float*)d_in[9];
    float* out = (float*)d_out;

    float *P, *T, *S;
    __nv_bfloat16 *Gb, *Eb, *Ob, *Wm;
    cudaGetSymbolAddress((void**)&P, g_P);
    cudaGetSymbolAddress((void**)&T, g_T);
    cudaGetSymbolAddress((void**)&S, g_S);
    cudaGetSymbolAddress((void**)&Gb, g_Gb);
    cudaGetSymbolAddress((void**)&Eb, g_Eb);
    cudaGetSymbolAddress((void**)&Ob, g_Ob);
    cudaGetSymbolAddress((void**)&Wm, g_Wm);

    const int smF  = smem_for(4, false);   // 70656
    const int smFT = smem_for(4, true);    // 67584
    const int smB  = smem_for(2, false);   // 71680

    cudaFuncSetAttribute((const void*)tc_gemm<float, false, 1>,
                         cudaFuncAttributeMaxDynamicSharedMemorySize, smF);
    cudaFuncSetAttribute((const void*)tc_gemm<float, false, 3>,
                         cudaFuncAttributeMaxDynamicSharedMemorySize, smF);
    cudaFuncSetAttribute((const void*)tc_gemm<float, true, 0>,
                         cudaFuncAttributeMaxDynamicSharedMemorySize, smFT);
    cudaFuncSetAttribute((const void*)tc_gemm<__nv_bfloat16, false, 4>,
                         cudaFuncAttributeMaxDynamicSharedMemorySize, smB);
    cudaFuncSetAttribute((const void*)tc_gemm<__nv_bfloat16, false, 2>,
                         cudaFuncAttributeMaxDynamicSharedMemorySize, smB);

    const dim3 blk(256);
    const long long sImg  = 512LL * 4096;   // x/y per-batch stride
    const long long sHalf = 256LL * 4096;   // conv-out per-batch stride (== 512*2048)
    const long long sS    = 2048LL * 2048;

    // w_mask -> bf16 (512*256 = 131072 elems)
    f2bf_kernel<<<128, 256>>>(w_mask, Wm, 131072 / 4);

    // conv1x1 (tf32): [256,512] x [512,4096] + bias
    tc_gemm<float, false, 1><<<dim3(32, 2, 8), blk, smF>>>(
        w_phi, y, P, b_phi, nullptr, 256, 4096, 512, 0, sImg, sHalf, 0);
    tc_gemm<float, false, 1><<<dim3(32, 2, 8), blk, smF>>>(
        w_theta, x, T, b_theta, nullptr, 256, 4096, 512, 0, sImg, sHalf, 0);
    tc_gemm<float, false, 3><<<dim3(32, 2, 8), blk, smF>>>(
        w_g, x, Gb, b_g, nullptr, 256, 4096, 512, 0, sImg, sHalf, 0);

    // S^T[m,n] = sum_c phi_v[c,m] * theta_v[c,n]   (tf32, A transposed [512,2048])
    tc_gemm<float, true, 0><<<dim3(16, 16, 8), blk, smFT>>>(
        P, T, S, nullptr, nullptr, 2048, 2048, 512, sHalf, sHalf, sS, 0);

    // softmax rows of S^T -> normalized bf16 attn
    softmax_rows_kernel<<<8 * 2048, 256>>>(S, Eb);

    // Out_v[c,n] = g_v[512,2048] @ E[2048,2048]  (bf16 in, bf16 out)
    tc_gemm<__nv_bfloat16, false, 4><<<dim3(16, 4, 8), blk, smB>>>(
        Gb, Eb, Ob, nullptr, nullptr, 512, 2048, 2048, sHalf, sS, sHalf, 0);

    // out = w_mask[512,256] @ Out(view [256,4096]) + b_mask + x  (bf16 in, fp32 out)
    tc_gemm<__nv_bfloat16, false, 2><<<dim3(32, 4, 8), blk, smB>>>(
        Wm, Ob, out, b_mask, x, 512, 4096, 256, 0, sHalf, sImg, sImg);
}

// round 11
// speedup vs baseline: 1.4470x; 1.0820x over previous
#include <cuda_runtime.h>
#include <cuda_bf16.h>
#include <mma.h>
#include <cstdint>
#include <type_traits>

using namespace nvcuda;

// ---- scratch ----
__device__ __align__(16) float         g_P[8u * 256u * 4096u];
__device__ __align__(16) float         g_T[8u * 256u * 4096u];
__device__ __align__(16) float         g_S[8u * 2048u * 2048u];
__device__ __align__(16) float         g_Wtg[512u * 512u];        // [w_theta; w_g] stacked
__device__ __align__(16) __nv_bfloat16 g_Gb[8u * 256u * 4096u];
__device__ __align__(16) __nv_bfloat16 g_Eb[8u * 2048u * 2048u];
__device__ __align__(16) __nv_bfloat16 g_Ob[8u * 256u * 4096u];
__device__ __align__(16) __nv_bfloat16 g_Wm[512u * 256u];

static __device__ __forceinline__ uint32_t s2u(const void* p) {
    uint32_t a;
    asm("{ .reg .u64 t; cvta.to.shared.u64 t, %1; cvt.u32.u64 %0, t; }" : "=r"(a) : "l"(p));
    return a;
}
static __device__ __forceinline__ void cpa16(uint32_t s, const void* g) {
    asm volatile("cp.async.cg.shared.global [%0], [%1], 16;" :: "r"(s), "l"(g));
}
static __device__ __forceinline__ void cpa_commit() {
    asm volatile("cp.async.commit_group;" ::: "memory");
}
template <int N>
static __device__ __forceinline__ void cpa_wait() {
    asm volatile("cp.async.wait_group %0;" :: "n"(N) : "memory");
}

template <typename T> struct WT;
template <> struct WT<float>         { static constexpr int KW = 8;  using AT = wmma::precision::tf32; };
template <> struct WT<__nv_bfloat16> { static constexpr int KW = 16; using AT = __nv_bfloat16; };

// ============================================================================
// 3-stage cp.async GEMM, 128x128 CTA tile, 256 thr, warp tile 64x32.
//   EPI: 0 fp32 | 1 fp32+bias | 2 fp32+bias+addend | 3 bf16+bias | 4 bf16
//        5 split: rows<256 -> fp32 Cg (+bias), rows>=256 -> bf16 Cg2 (+addend as bias)
// ============================================================================
template <typename T, bool TRANS_A, int EPI>
__global__ __launch_bounds__(256, 2)
void tc_gemm(const void* __restrict__ Ag, const void* __restrict__ Bg,
             void* __restrict__ Cg, void* __restrict__ Cg2,
             const float* __restrict__ bias, const float* __restrict__ addend,
             int M, int N, int K,
             long long sA, long long sB, long long sC, long long sAdd)
{
    constexpr int S   = 3;
    constexpr int CK  = 128 / (int)sizeof(T);
    constexpr int PAD = 16 / (int)sizeof(T);
    constexpr int EPR = 16 / (int)sizeof(T);
    constexpr int LDA = TRANS_A ? (128 + PAD) : (CK + PAD);
    constexpr int LDB = 128 + PAD;
    constexpr int ASZ = (TRANS_A ? CK * (128 + PAD) : 128 * (CK + PAD)) * (int)sizeof(T);
    constexpr int BSZ = CK * (128 + PAD) * (int)sizeof(T);
    constexpr int STG = ASZ + BSZ;
    using AMaj = typename std::conditional<TRANS_A, wmma::col_major, wmma::row_major>::type;

    extern __shared__ __align__(16) char sm[];

    const int tid = threadIdx.x, warpId = tid >> 5, lane = tid & 31;
    const int wm = warpId >> 2, wn = warpId & 3;
    const int bn0 = blockIdx.x * 128, bm0 = blockIdx.y * 128, batch = blockIdx.z;
    const T* Ab = (const T*)Ag + (long long)batch * sA;
    const T* Bb = (const T*)Bg + (long long)batch * sB;

    wmma::fragment<wmma::accumulator, 16, 16, WT<T>::KW, float> acc[4][2];
#pragma unroll
    for (int i = 0; i < 4; i++)
#pragma unroll
        for (int j = 0; j < 2; j++) wmma::fill_fragment(acc[i][j], 0.0f);

    auto stage = [&](int k0, int slot) {
        char* At = sm + slot * STG;
        char* Bt = At + ASZ;
        if (TRANS_A) {
            constexpr int CPR = 128 / EPR;
#pragma unroll
            for (int u = 0; u < CK * CPR / 256; u++) {
                int s = tid + u * 256;
                int r = s / CPR, c = s % CPR;
                cpa16(s2u(At + (r * LDA + c * EPR) * sizeof(T)),
                      Ab + (long long)(k0 + r) * M + bm0 + c * EPR);
            }
        } else {
            constexpr int CPR = CK / EPR;
#pragma unroll
            for (int u = 0; u < 128 * CPR / 256; u++) {
                int s = tid + u * 256;
                int r = s / CPR, c = s % CPR;
                cpa16(s2u(At + (r * LDA + c * EPR) * sizeof(T)),
                      Ab + (long long)(bm0 + r) * K + k0 + c * EPR);
            }
        }
        {
            constexpr int CPR = 128 / EPR;
#pragma unroll
            for (int u = 0; u < CK * CPR / 256; u++) {
                int s = tid + u * 256;
                int r = s / CPR, c = s % CPR;
                cpa16(s2u(Bt + (r * LDB + c * EPR) * sizeof(T)),
                      Bb + (long long)(k0 + r) * N + bn0 + c * EPR);
            }
        }
        cpa_commit();
    };

    const int NC = K / CK;
    stage(0, 0);
    if (NC > 1) stage(CK, 1);

    for (int i = 0; i < NC; i++) {
        if (i < NC - (S - 1)) cpa_wait<S - 2>();
        else                  cpa_wait<0>();
        __syncthreads();

        const T* As = (const T*)(sm + (i % S) * STG);
        const T* Bs = (const T*)(sm + (i % S) * STG + ASZ);
#pragma unroll
        for (int kk = 0; kk < CK; kk += WT<T>::KW) {
            wmma::fragment<wmma::matrix_a, 16, 16, WT<T>::KW, typename WT<T>::AT, AMaj> af[4];
            wmma::fragment<wmma::matrix_b, 16, 16, WT<T>::KW, typename WT<T>::AT,
                           wmma::row_major> bf[2];
#pragma unroll
            for (int i2 = 0; i2 < 4; i2++) {
                const T* p = TRANS_A ? &As[kk * LDA + wm * 64 + i2 * 16]
                                     : &As[(wm * 64 + i2 * 16) * LDA + kk];
                wmma::load_matrix_sync(af[i2], p, LDA);
            }
#pragma unroll
            for (int j = 0; j < 2; j++)
                wmma::load_matrix_sync(bf[j], &Bs[kk * LDB + wn * 32 + j * 16], LDB);
#pragma unroll
            for (int i2 = 0; i2 < 4; i2++)
#pragma unroll
                for (int j = 0; j < 2; j++)
                    wmma::mma_sync(acc[i2][j], af[i2], bf[j], acc[i2][j]);
        }
        if (i + S - 1 < NC) stage((i + S - 1) * CK, (i + S - 1) % S);
    }
    __syncthreads();

    // ---- epilogue ----
    if (EPI == 0) {
        float* Cb = (float*)Cg + (long long)batch * sC;
#pragma unroll
        for (int i = 0; i < 4; i++)
#pragma unroll
            for (int j = 0; j < 2; j++)
                wmma::store_matrix_sync(
                    Cb + (long long)(bm0 + wm * 64 + i * 16) * N + bn0 + wn * 32 + j * 16,
                    acc[i][j], N, wmma::mem_row_major);
    } else {
        float* epi = (float*)sm + warpId * 256;
#pragma unroll
        for (int i = 0; i < 4; i++)
#pragma unroll
            for (int j = 0; j < 2; j++) {
                wmma::store_matrix_sync(epi, acc[i][j], 16, wmma::mem_row_major);
                __syncwarp();
#pragma unroll
                for (int e = 0; e < 8; e++) {
                    int idx = lane * 8 + e;
                    int r = idx >> 4, cl = idx & 15;
                    int gm = bm0 + wm * 64 + i * 16 + r;
                    int gn = bn0 + wn * 32 + j * 16 + cl;
                    float v = epi[idx];
                    if (EPI == 5) {
                        if (gm < 256) {
                            ((float*)Cg + (long long)batch * sC)[(long long)gm * N + gn] =
                                v + bias[gm];
                        } else {
                            ((__nv_bfloat16*)Cg2 + (long long)batch * sAdd)
                                [(long long)(gm - 256) * N + gn] =
                                __float2bfloat16(v + addend[gm - 256]);
                        }
                    } else {
                        if (EPI == 1 || EPI == 2 || EPI == 3) v += bias[gm];
                        if (EPI == 2)
                            v += addend[(long long)batch * sAdd + (long long)gm * N + gn];
                        if (EPI == 3 || EPI == 4)
                            ((__nv_bfloat16*)Cg + (long long)batch * sC)[(long long)gm * N + gn] =
                                __float2bfloat16(v);
                        else
                            ((float*)Cg + (long long)batch * sC)[(long long)gm * N + gn] = v;
                    }
                }
                __syncwarp();
            }
    }
}

// ============================================================================
__global__ void softmax_rows_kernel(const float* __restrict__ S,
                                    __nv_bfloat16* __restrict__ E)
{
    const float* row = S + (size_t)blockIdx.x * 2048u;
    __nv_bfloat16* er = E + (size_t)blockIdx.x * 2048u;
    const int tid = threadIdx.x, lane = tid & 31, warp = tid >> 5;

    float4 a = reinterpret_cast<const float4*>(row)[tid];
    float4 b = reinterpret_cast<const float4*>(row)[tid + 256];

    float m = fmaxf(fmaxf(fmaxf(a.x, a.y), fmaxf(a.z, a.w)),
                    fmaxf(fmaxf(b.x, b.y), fmaxf(b.z, b.w)));
#pragma unroll
    for (int o = 16; o > 0; o >>= 1) m = fmaxf(m, __shfl_xor_sync(0xffffffffu, m, o));

    __shared__ float red[8];
    if (lane == 0) red[warp] = m;
    __syncthreads();
    float rm = red[0];
#pragma unroll
    for (int i = 1; i < 8; i++) rm = fmaxf(rm, red[i]);
    __syncthreads();

    a.x = __expf(a.x - rm); a.y = __expf(a.y - rm);
    a.z = __expf(a.z - rm); a.w = __expf(a.w - rm);
    b.x = __expf(b.x - rm); b.y = __expf(b.y - rm);
    b.z = __expf(b.z - rm); b.w = __expf(b.w - rm);

    float s = a.x + a.y + a.z + a.w + b.x + b.y + b.z + b.w;
#pragma unroll
    for (int o = 16; o > 0; o >>= 1) s += __shfl_xor_sync(0xffffffffu, s, o);
    if (lane == 0) red[warp] = s;
    __syncthreads();
    float rs = red[0];
#pragma unroll
    for (int i = 1; i < 8; i++) rs += red[i];

    float inv = 1.0f / rs;
    __nv_bfloat162 h0 = __floats2bfloat162_rn(a.x * inv, a.y * inv);
    __nv_bfloat162 h1 = __floats2bfloat162_rn(a.z * inv, a.w * inv);
    __nv_bfloat162 h2 = __floats2bfloat162_rn(b.x * inv, b.y * inv);
    __nv_bfloat162 h3 = __floats2bfloat162_rn(b.z * inv, b.w * inv);
    reinterpret_cast<uint2*>(er)[tid]       = make_uint2(*(uint32_t*)&h0, *(uint32_t*)&h1);
    reinterpret_cast<uint2*>(er)[tid + 256] = make_uint2(*(uint32_t*)&h2, *(uint32_t*)&h3);
}

__global__ void f2bf_kernel(const float* __restrict__ in,
                            __nv_bfloat16* __restrict__ out, int n4)
{
    int i = blockIdx.x * blockDim.x + threadIdx.x;
    if (i < n4) {
        float4 v = reinterpret_cast<const float4*>(in)[i];
        __nv_bfloat162 h0 = __floats2bfloat162_rn(v.x, v.y);
        __nv_bfloat162 h1 = __floats2bfloat162_rn(v.z, v.w);
        reinterpret_cast<uint2*>(out)[i] = make_uint2(*(uint32_t*)&h0, *(uint32_t*)&h1);
    }
}

// stack [w_theta; w_g] into g_Wtg ([512,512])
__global__ void pack_wtg_kernel(const float* __restrict__ wt, const float* __restrict__ wg,
                                float* __restrict__ out)
{
    int i = blockIdx.x * blockDim.x + threadIdx.x;   // float4 index over 2*131072
    float4 v = (i < 32768) ? reinterpret_cast<const float4*>(wt)[i]
                           : reinterpret_cast<const float4*>(wg)[i - 32768];
    reinterpret_cast<float4*>(out)[i] = v;
}

// ============================================================================
static constexpr int smem_for(int szT, bool trans)
{
    int CK = 128 / szT, PAD = 16 / szT;
    int A = (trans ? CK * (128 + PAD) : 128 * (CK + PAD)) * szT;
    int B = CK * (128 + PAD) * szT;
    return 3 * (A + B);
}

extern "C" void kernel_launch(void* const* d_in, const int* in_sizes, int n_in,
                              void* d_out, int out_size)
{
    const float* x       = (const float*)d_in[0];
    const float* y       = (const float*)d_in[1];
    const float* w_phi   = (const float*)d_in[2];
    const float* b_phi   = (const float*)d_in[3];
    const float* w_theta = (const float*)d_in[4];
    const float* b_theta = (const float*)d_in[5];
    const float* w_g     = (const float*)d_in[6];
    const float* b_g     = (const float*)d_in[7];
    const float* w_mask  = (const float*)d_in[8];
    const float* b_mask  = (const float*)d_in[9];
    float* out = (float*)d_out;

    float *P, *T, *S, *Wtg;
    __nv_bfloat16 *Gb, *Eb, *Ob, *Wm;
    cudaGetSymbolAddress((void**)&P, g_P);
    cudaGetSymbolAddress((void**)&T, g_T);
    cudaGetSymbolAddress((void**)&S, g_S);
    cudaGetSymbolAddress((void**)&Wtg, g_Wtg);
    cudaGetSymbolAddress((void**)&Gb, g_Gb);
    cudaGetSymbolAddress((void**)&Eb, g_Eb);
    cudaGetSymbolAddress((void**)&Ob, g_Ob);
    cudaGetSymbolAddress((void**)&Wm, g_Wm);

    const int smF  = smem_for(4, false);   // 105984
    const int smFT = smem_for(4, true);    // 101376
    const int smB  = smem_for(2, false);   // 107520

    cudaFuncSetAttribute((const void*)tc_gemm<float, false, 1>,
                         cudaFuncAttributeMaxDynamicSharedMemorySize, smF);
    cudaFuncSetAttribute((const void*)tc_gemm<float, false, 5>,
                         cudaFuncAttributeMaxDynamicSharedMemorySize, smF);
    cudaFuncSetAttribute((const void*)tc_gemm<float, true, 0>,
                         cudaFuncAttributeMaxDynamicSharedMemorySize, smFT);
    cudaFuncSetAttribute((const void*)tc_gemm<__nv_bfloat16, false, 4>,
                         cudaFuncAttributeMaxDynamicSharedMemorySize, smB);
    cudaFuncSetAttribute((const void*)tc_gemm<__nv_bfloat16, false, 2>,
                         cudaFuncAttributeMaxDynamicSharedMemorySize, smB);

    const dim3 blk(256);
    const long long sImg  = 512LL * 4096;
    const long long sHalf = 256LL * 4096;
    const long long sS    = 2048LL * 2048;

    f2bf_kernel<<<128, 256>>>(w_mask, Wm, 131072 / 4);
    pack_wtg_kernel<<<256, 256>>>(w_theta, w_g, Wtg);

    // phi conv (tf32): [256,512] x y + b_phi -> P fp32
    tc_gemm<float, false, 1><<<dim3(32, 2, 8), blk, smF>>>(
        w_phi, y, P, nullptr, b_phi, nullptr, 256, 4096, 512, 0, sImg, sHalf, 0);

    // merged theta+g conv: [512,512] x x; rows<256 -> T fp32 (+b_theta),
    // rows>=256 -> Gb bf16 (+b_g)
    tc_gemm<float, false, 5><<<dim3(32, 4, 8), blk, smF>>>(
        Wtg, x, T, Gb, b_theta, b_g, 512, 4096, 512, 0, sImg, sHalf, sHalf);

    // S^T = P^T(view) @ T(view): tf32, A trans [512,2048]
    tc_gemm<float, true, 0><<<dim3(16, 16, 8), blk, smFT>>>(
        P, T, S, nullptr, nullptr, nullptr, 2048, 2048, 512, sHalf, sHalf, sS, 0);

    // softmax rows of S^T -> bf16 attn
    softmax_rows_kernel<<<8 * 2048, 256>>>(S, Eb);

    // Out_v = g_v[512,2048] @ E[2048,2048] (bf16)
    tc_gemm<__nv_bfloat16, false, 4><<<dim3(16, 4, 8), blk, smB>>>(
        Gb, Eb, Ob, nullptr, nullptr, nullptr, 512, 2048, 2048, sHalf, sS, sHalf, 0);

    // out = Wm[512,256] @ Ob(view [256,4096]) + b_mask + x (fp32 out)
    tc_gemm<__nv_bfloat16, false, 2><<<dim3(32, 4, 8), blk, smB>>>(
        Wm, Ob, out, nullptr, b_mask, x, 512, 4096, 256, 0, sHalf, sImg, sImg);
}

// round 13
// speedup vs baseline: 2.3786x; 1.6438x over previous
#include <cuda_runtime.h>
#include <cuda_bf16.h>
#include <mma.h>
#include <cstdint>
#include <type_traits>

using namespace nvcuda;

// ---- scratch (__device__ globals; no allocations allowed) ----
__device__ __align__(16) __nv_bfloat16 g_Xb[8u * 2097152u];   // x bf16 [512,4096]/b
__device__ __align__(16) __nv_bfloat16 g_Yb[8u * 2097152u];   // y bf16
__device__ __align__(16) __nv_bfloat16 g_P[8u * 1048576u];    // phi conv out bf16 (viewed [512,2048]/b)
__device__ __align__(16) __nv_bfloat16 g_T[8u * 1048576u];    // theta conv out bf16
__device__ __align__(16) __nv_bfloat16 g_Gb[8u * 1048576u];   // g conv out bf16
__device__ __align__(16) float         g_S[8u * 4194304u];    // S^T fp32 scores
__device__ __align__(16) __nv_bfloat16 g_Eb[8u * 4194304u];   // normalized attn bf16
__device__ __align__(16) __nv_bfloat16 g_Ob[8u * 1048576u];   // O out bf16 (viewed [256,4096]/b)
__device__ __align__(16) __nv_bfloat16 g_Wtg[262144u];        // [w_theta; w_g] bf16
__device__ __align__(16) __nv_bfloat16 g_Wp[131072u];         // w_phi bf16
__device__ __align__(16) __nv_bfloat16 g_Wm[131072u];         // w_mask bf16

// ---- helpers ----
static __device__ __forceinline__ uint32_t s2u(const void* p) {
    uint32_t a;
    asm("{ .reg .u64 t; cvta.to.shared.u64 t, %1; cvt.u32.u64 %0, t; }" : "=r"(a) : "l"(p));
    return a;
}
static __device__ __forceinline__ void cpa16(uint32_t s, const void* g) {
    asm volatile("cp.async.cg.shared.global [%0], [%1], 16;" :: "r"(s), "l"(g));
}
static __device__ __forceinline__ void cpa_commit() {
    asm volatile("cp.async.commit_group;" ::: "memory");
}
template <int N>
static __device__ __forceinline__ void cpa_wait() {
    asm volatile("cp.async.wait_group %0;" :: "n"(N) : "memory");
}

// ============================================================================
// 3-stage cp.async bf16 GEMM, 128x128 CTA tile, 256 thr, warp tile 64x32.
//   A: TRANS_A ? [K,M] (lda=M) : [M,K] (lda=K);  B: [K,N] row-major. bf16.
//   EPI: 0 fp32 plain | 2 fp32+bias[gm]+addend | 3 bf16+bias[gm] | 4 bf16 plain
//        5 split: gm<256 -> bf16 Cg +bias; gm>=256 -> bf16 Cg2 +bias2[gm-256]
// ============================================================================
template <bool TRANS_A, int EPI>
__global__ __launch_bounds__(256, 2)
void tc_gemm(const __nv_bfloat16* __restrict__ Ag, const __nv_bfloat16* __restrict__ Bg,
             void* __restrict__ Cg, void* __restrict__ Cg2,
             const float* __restrict__ bias, const float* __restrict__ bias2,
             const float* __restrict__ addend, int M, int N, int K,
             long long sA, long long sB, long long sC, long long sAdd)
{
    constexpr int S   = 3;
    constexpr int CK  = 64;                    // K elems per chunk (128B)
    constexpr int PAD = 8;
    constexpr int EPR = 8;                     // bf16 per 16B
    constexpr int LDA = TRANS_A ? (128 + PAD) : (CK + PAD);
    constexpr int LDB = 128 + PAD;
    constexpr int ASZ = (TRANS_A ? CK * (128 + PAD) : 128 * (CK + PAD)) * 2;
    constexpr int BSZ = CK * (128 + PAD) * 2;
    constexpr int STG = ASZ + BSZ;
    using AMaj = typename std::conditional<TRANS_A, wmma::col_major, wmma::row_major>::type;

    extern __shared__ __align__(16) char sm[];

    const int tid = threadIdx.x, warpId = tid >> 5, lane = tid & 31;
    const int wm = warpId >> 2, wn = warpId & 3;
    const int bn0 = blockIdx.x * 128, bm0 = blockIdx.y * 128, batch = blockIdx.z;
    const __nv_bfloat16* Ab = Ag + (long long)batch * sA;
    const __nv_bfloat16* Bb = Bg + (long long)batch * sB;

    wmma::fragment<wmma::accumulator, 16, 16, 16, float> acc[4][2];
#pragma unroll
    for (int i = 0; i < 4; i++)
#pragma unroll
        for (int j = 0; j < 2; j++) wmma::fill_fragment(acc[i][j], 0.0f);

    auto stage = [&](int k0, int slot) {
        char* At = sm + slot * STG;
        char* Bt = At + ASZ;
        if (TRANS_A) {
            constexpr int CPR = 128 / EPR;   // 16
#pragma unroll
            for (int u = 0; u < CK * CPR / 256; u++) {
                int s = tid + u * 256;
                int r = s / CPR, c = s % CPR;
                cpa16(s2u(At + (r * LDA + c * EPR) * 2),
                      Ab + (long long)(k0 + r) * M + bm0 + c * EPR);
            }
        } else {
            constexpr int CPR = CK / EPR;    // 8
#pragma unroll
            for (int u = 0; u < 128 * CPR / 256; u++) {
                int s = tid + u * 256;
                int r = s / CPR, c = s % CPR;
                cpa16(s2u(At + (r * LDA + c * EPR) * 2),
                      Ab + (long long)(bm0 + r) * K + k0 + c * EPR);
            }
        }
        {
            constexpr int CPR = 128 / EPR;   // 16
#pragma unroll
            for (int u = 0; u < CK * CPR / 256; u++) {
                int s = tid + u * 256;
                int r = s / CPR, c = s % CPR;
                cpa16(s2u(Bt + (r * LDB + c * EPR) * 2),
                      Bb + (long long)(k0 + r) * N + bn0 + c * EPR);
            }
        }
        cpa_commit();
    };

    const int NC = K / CK;
    stage(0, 0);
    if (NC > 1) stage(CK, 1);

    for (int i = 0; i < NC; i++) {
        if (i < NC - (S - 1)) cpa_wait<S - 2>();
        else                  cpa_wait<0>();
        __syncthreads();

        const __nv_bfloat16* As = (const __nv_bfloat16*)(sm + (i % S) * STG);
        const __nv_bfloat16* Bs = (const __nv_bfloat16*)(sm + (i % S) * STG + ASZ);
#pragma unroll
        for (int kk = 0; kk < CK; kk += 16) {
            wmma::fragment<wmma::matrix_a, 16, 16, 16, __nv_bfloat16, AMaj> af[4];
            wmma::fragment<wmma::matrix_b, 16, 16, 16, __nv_bfloat16, wmma::row_major> bf[2];
#pragma unroll
            for (int i2 = 0; i2 < 4; i2++) {
                const __nv_bfloat16* p = TRANS_A ? &As[kk * LDA + wm * 64 + i2 * 16]
                                                 : &As[(wm * 64 + i2 * 16) * LDA + kk];
                wmma::load_matrix_sync(af[i2], p, LDA);
            }
#pragma unroll
            for (int j = 0; j < 2; j++)
                wmma::load_matrix_sync(bf[j], &Bs[kk * LDB + wn * 32 + j * 16], LDB);
#pragma unroll
            for (int i2 = 0; i2 < 4; i2++)
#pragma unroll
                for (int j = 0; j < 2; j++)
                    wmma::mma_sync(acc[i2][j], af[i2], bf[j], acc[i2][j]);
        }
        if (i + S - 1 < NC) stage((i + S - 1) * CK, (i + S - 1) % S);
    }
    __syncthreads();

    // ---- epilogue ----
    if (EPI == 0) {
        float* Cb = (float*)Cg + (long long)batch * sC;
#pragma unroll
        for (int i = 0; i < 4; i++)
#pragma unroll
            for (int j = 0; j < 2; j++)
                wmma::store_matrix_sync(
                    Cb + (long long)(bm0 + wm * 64 + i * 16) * N + bn0 + wn * 32 + j * 16,
                    acc[i][j], N, wmma::mem_row_major);
    } else {
        float* epi = (float*)sm + warpId * 256;
#pragma unroll
        for (int i = 0; i < 4; i++)
#pragma unroll
            for (int j = 0; j < 2; j++) {
                wmma::store_matrix_sync(epi, acc[i][j], 16, wmma::mem_row_major);
                __syncwarp();
#pragma unroll
                for (int e = 0; e < 8; e++) {
                    int idx = lane * 8 + e;
                    int r = idx >> 4, cl = idx & 15;
                    int gm = bm0 + wm * 64 + i * 16 + r;
                    int gn = bn0 + wn * 32 + j * 16 + cl;
                    float v = epi[idx];
                    if (EPI == 5) {
                        if (gm < 256)
                            ((__nv_bfloat16*)Cg + (long long)batch * sC)[(long long)gm * N + gn] =
                                __float2bfloat16(v + bias[gm]);
                        else
                            ((__nv_bfloat16*)Cg2 + (long long)batch * sAdd)
                                [(long long)(gm - 256) * N + gn] =
                                __float2bfloat16(v + bias2[gm - 256]);
                    } else if (EPI == 2) {
                        v += bias[gm] +
                             addend[(long long)batch * sAdd + (long long)gm * N + gn];
                        ((float*)Cg + (long long)batch * sC)[(long long)gm * N + gn] = v;
                    } else if (EPI == 3) {
                        ((__nv_bfloat16*)Cg + (long long)batch * sC)[(long long)gm * N + gn] =
                            __float2bfloat16(v + bias[gm]);
                    } else {  // EPI == 4
                        ((__nv_bfloat16*)Cg + (long long)batch * sC)[(long long)gm * N + gn] =
                            __float2bfloat16(v);
                    }
                }
                __syncwarp();
            }
    }
}

// ============================================================================
// Row softmax over S^T rows (2048 fp32) -> normalized bf16 attn.
// ============================================================================
__global__ void softmax_rows_kernel(const float* __restrict__ S,
                                    __nv_bfloat16* __restrict__ E)
{
    const float* row = S + (size_t)blockIdx.x * 2048u;
    __nv_bfloat16* er = E + (size_t)blockIdx.x * 2048u;
    const int tid = threadIdx.x, lane = tid & 31, warp = tid >> 5;

    float4 a = reinterpret_cast<const float4*>(row)[tid];
    float4 b = reinterpret_cast<const float4*>(row)[tid + 256];

    float m = fmaxf(fmaxf(fmaxf(a.x, a.y), fmaxf(a.z, a.w)),
                    fmaxf(fmaxf(b.x, b.y), fmaxf(b.z, b.w)));
#pragma unroll
    for (int o = 16; o > 0; o >>= 1) m = fmaxf(m, __shfl_xor_sync(0xffffffffu, m, o));

    __shared__ float red[8];
    if (lane == 0) red[warp] = m;
    __syncthreads();
    float rm = red[0];
#pragma unroll
    for (int i = 1; i < 8; i++) rm = fmaxf(rm, red[i]);
    __syncthreads();

    a.x = __expf(a.x - rm); a.y = __expf(a.y - rm);
    a.z = __expf(a.z - rm); a.w = __expf(a.w - rm);
    b.x = __expf(b.x - rm); b.y = __expf(b.y - rm);
    b.z = __expf(b.z - rm); b.w = __expf(b.w - rm);

    float s = a.x + a.y + a.z + a.w + b.x + b.y + b.z + b.w;
#pragma unroll
    for (int o = 16; o > 0; o >>= 1) s += __shfl_xor_sync(0xffffffffu, s, o);
    if (lane == 0) red[warp] = s;
    __syncthreads();
    float rs = red[0];
#pragma unroll
    for (int i = 1; i < 8; i++) rs += red[i];

    float inv = 1.0f / rs;
    __nv_bfloat162 h0 = __floats2bfloat162_rn(a.x * inv, a.y * inv);
    __nv_bfloat162 h1 = __floats2bfloat162_rn(a.z * inv, a.w * inv);
    __nv_bfloat162 h2 = __floats2bfloat162_rn(b.x * inv, b.y * inv);
    __nv_bfloat162 h3 = __floats2bfloat162_rn(b.z * inv, b.w * inv);
    reinterpret_cast<uint2*>(er)[tid]       = make_uint2(*(uint32_t*)&h0, *(uint32_t*)&h1);
    reinterpret_cast<uint2*>(er)[tid + 256] = make_uint2(*(uint32_t*)&h2, *(uint32_t*)&h3);
}

// fp32 -> bf16 pack (grid-stride)
__global__ void f2bf_kernel(const float* __restrict__ in,
                            __nv_bfloat16* __restrict__ out, int n4)
{
    for (int i = blockIdx.x * blockDim.x + threadIdx.x; i < n4; i += gridDim.x * blockDim.x) {
        float4 v = reinterpret_cast<const float4*>(in)[i];
        __nv_bfloat162 h0 = __floats2bfloat162_rn(v.x, v.y);
        __nv_bfloat162 h1 = __floats2bfloat162_rn(v.z, v.w);
        reinterpret_cast<uint2*>(out)[i] = make_uint2(*(uint32_t*)&h0, *(uint32_t*)&h1);
    }
}

// stack [w_theta; w_g] -> bf16 [512,512]
__global__ void pack_wtg_kernel(const float* __restrict__ wt, const float* __restrict__ wg,
                                __nv_bfloat16* __restrict__ out)
{
    int i = blockIdx.x * blockDim.x + threadIdx.x;  // float4 slots over 2*32768
    float4 v = (i < 32768) ? reinterpret_cast<const float4*>(wt)[i]
                           : reinterpret_cast<const float4*>(wg)[i - 32768];
    __nv_bfloat162 h0 = __floats2bfloat162_rn(v.x, v.y);
    __nv_bfloat162 h1 = __floats2bfloat162_rn(v.z, v.w);
    reinterpret_cast<uint2*>(out)[i] = make_uint2(*(uint32_t*)&h0, *(uint32_t*)&h1);
}

// ============================================================================
extern "C" void kernel_launch(void* const* d_in, const int* in_sizes, int n_in,
                              void* d_out, int out_size)
{
    const float* x       = (const float*)d_in[0];
    const float* y       = (const float*)d_in[1];
    const float* w_phi   = (const float*)d_in[2];
    const float* b_phi   = (const float*)d_in[3];
    const float* w_theta = (const float*)d_in[4];
    const float* b_theta = (const float*)d_in[5];
    const float* w_g     = (const float*)d_in[6];
    const float* b_g     = (const float*)d_in[7];
    const float* w_mask  = (const float*)d_in[8];
    const float* b_mask  = (const float*)d_in[9];
    float* out = (float*)d_out;

    float* S;
    __nv_bfloat16 *Xb, *Yb, *P, *T, *Gb, *Eb, *Ob, *Wtg, *Wp, *Wm;
    cudaGetSymbolAddress((void**)&Xb, g_Xb);
    cudaGetSymbolAddress((void**)&Yb, g_Yb);
    cudaGetSymbolAddress((void**)&P,  g_P);
    cudaGetSymbolAddress((void**)&T,  g_T);
    cudaGetSymbolAddress((void**)&Gb, g_Gb);
    cudaGetSymbolAddress((void**)&S,  g_S);
    cudaGetSymbolAddress((void**)&Eb, g_Eb);
    cudaGetSymbolAddress((void**)&Ob, g_Ob);
    cudaGetSymbolAddress((void**)&Wtg, g_Wtg);
    cudaGetSymbolAddress((void**)&Wp, g_Wp);
    cudaGetSymbolAddress((void**)&Wm, g_Wm);

    // smem: nontrans = 3*(128*72 + 64*136)*2 = 107520 ; trans = 3*(64*136*2)*2 = 104448
    const int smN = 3 * (128 * 72 + 64 * 136) * 2;
    const int smT = 3 * (2 * 64 * 136) * 2;

    cudaFuncSetAttribute((const void*)tc_gemm<false, 3>,
                         cudaFuncAttributeMaxDynamicSharedMemorySize, smN);
    cudaFuncSetAttribute((const void*)tc_gemm<false, 5>,
                         cudaFuncAttributeMaxDynamicSharedMemorySize, smN);
    cudaFuncSetAttribute((const void*)tc_gemm<true, 0>,
                         cudaFuncAttributeMaxDynamicSharedMemorySize, smT);
    cudaFuncSetAttribute((const void*)tc_gemm<false, 4>,
                         cudaFuncAttributeMaxDynamicSharedMemorySize, smN);
    cudaFuncSetAttribute((const void*)tc_gemm<false, 2>,
                         cudaFuncAttributeMaxDynamicSharedMemorySize, smN);

    const dim3 blk(256);
    const long long sImg  = 512LL * 4096;   // fp32 x/y per-batch stride (elements)
    const long long sHalf = 256LL * 4096;   // conv-out per-batch stride
    const long long sS    = 2048LL * 2048;

    // packs: weights + x,y to bf16
    f2bf_kernel<<<128, 256>>>(w_phi,  Wp, 131072 / 4);
    f2bf_kernel<<<128, 256>>>(w_mask, Wm, 131072 / 4);
    pack_wtg_kernel<<<256, 256>>>(w_theta, w_g, Wtg);
    f2bf_kernel<<<2048, 256>>>(x, Xb, (int)(8 * sImg / 4));
    f2bf_kernel<<<2048, 256>>>(y, Yb, (int)(8 * sImg / 4));

    // phi conv: Wp[256,512] x Yb[512,4096] + b_phi -> P bf16
    tc_gemm<false, 3><<<dim3(32, 2, 8), blk, smN>>>(
        Wp, Yb, P, nullptr, b_phi, nullptr, nullptr,
        256, 4096, 512, 0, sImg, sHalf, 0);

    // merged theta+g conv: Wtg[512,512] x Xb; rows<256 -> T (+b_theta), rows>=256 -> Gb (+b_g)
    tc_gemm<false, 5><<<dim3(32, 4, 8), blk, smN>>>(
        Wtg, Xb, T, Gb, b_theta, b_g, nullptr,
        512, 4096, 512, 0, sImg, sHalf, sHalf);

    // S^T[m,n] = sum_c P_v[c,m] * T_v[c,n]  (A trans [512,2048], fp32 out)
    tc_gemm<true, 0><<<dim3(16, 16, 8), blk, smT>>>(
        P, T, S, nullptr, nullptr, nullptr, nullptr,
        2048, 2048, 512, sHalf, sHalf, sS, 0);

    // softmax rows of S^T -> normalized bf16 attn
    softmax_rows_kernel<<<8 * 2048, 256>>>(S, Eb);

    // Out_v = g_v[512,2048] @ E[2048,2048] -> Ob bf16
    tc_gemm<false, 4><<<dim3(16, 4, 8), blk, smN>>>(
        Gb, Eb, Ob, nullptr, nullptr, nullptr, nullptr,
        512, 2048, 2048, sHalf, sS, sHalf, 0);

    // out = Wm[512,256] @ Ob(view [256,4096]) + b_mask + x  (fp32 out)
    tc_gemm<false, 2><<<dim3(32, 4, 8), blk, smN>>>(
        Wm, Ob, out, nullptr, b_mask, nullptr, x,
        512, 4096, 256, 0, sHalf, sImg, sImg);
}

// round 15
// speedup vs baseline: 2.9898x; 1.2570x over previous
#include <cuda_runtime.h>
#include <cuda_bf16.h>
#include <mma.h>
#include <cstdint>
#include <type_traits>

using namespace nvcuda;

// ---- scratch (__device__ globals; no allocations allowed) ----
__device__ __align__(16) __nv_bfloat16 g_Xb[8u * 2097152u];   // x bf16 [512,4096]/b
__device__ __align__(16) __nv_bfloat16 g_Yb[8u * 2097152u];   // y bf16
__device__ __align__(16) __nv_bfloat16 g_P[8u * 1048576u];    // phi conv out bf16 (viewed [512,2048]/b)
__device__ __align__(16) __nv_bfloat16 g_T[8u * 1048576u];    // theta conv out bf16
__device__ __align__(16) __nv_bfloat16 g_Gb[8u * 1048576u];   // g conv out bf16
__device__ __align__(16) float         g_S[8u * 4194304u];    // S^T fp32 scores
__device__ __align__(16) __nv_bfloat16 g_Eb[8u * 4194304u];   // normalized attn bf16
__device__ __align__(16) __nv_bfloat16 g_Ob[8u * 1048576u];   // O out bf16 (viewed [256,4096]/b)
__device__ __align__(16) __nv_bfloat16 g_Wtg[262144u];        // [w_theta; w_g] bf16
__device__ __align__(16) __nv_bfloat16 g_Wp[131072u];         // w_phi bf16
__device__ __align__(16) __nv_bfloat16 g_Wm[131072u];         // w_mask bf16

// ---- helpers ----
static __device__ __forceinline__ uint32_t s2u(const void* p) {
    uint32_t a;
    asm("{ .reg .u64 t; cvta.to.shared.u64 t, %1; cvt.u32.u64 %0, t; }" : "=r"(a) : "l"(p));
    return a;
}
static __device__ __forceinline__ void cpa16(uint32_t s, const void* g) {
    asm volatile("cp.async.cg.shared.global [%0], [%1], 16;" :: "r"(s), "l"(g));
}
static __device__ __forceinline__ void cpa_commit() {
    asm volatile("cp.async.commit_group;" ::: "memory");
}
template <int N>
static __device__ __forceinline__ void cpa_wait() {
    asm volatile("cp.async.wait_group %0;" :: "n"(N) : "memory");
}
static __device__ __forceinline__ uint4 pack8_bf16(float4 v0, float4 v1, float add) {
    uint4 o;
    __nv_bfloat162 h;
    h = __floats2bfloat162_rn(v0.x + add, v0.y + add); o.x = *(uint32_t*)&h;
    h = __floats2bfloat162_rn(v0.z + add, v0.w + add); o.y = *(uint32_t*)&h;
    h = __floats2bfloat162_rn(v1.x + add, v1.y + add); o.z = *(uint32_t*)&h;
    h = __floats2bfloat162_rn(v1.z + add, v1.w + add); o.w = *(uint32_t*)&h;
    return o;
}

// ============================================================================
// 3-stage cp.async bf16 GEMM, 128x128 CTA tile, 256 thr, warp tile 64x32.
//   A: TRANS_A ? [K,M] (lda=M) : [M,K] (lda=K);  B: [K,N] row-major. bf16.
//   EPI: 0 fp32 plain | 2 fp32+bias[gm]+addend | 3 bf16+bias[gm] | 4 bf16 plain
//        5 split: gm<256 -> bf16 Cg +bias; gm>=256 -> bf16 Cg2 +bias2[gm-256]
// ============================================================================
template <bool TRANS_A, int EPI>
__global__ __launch_bounds__(256, 2)
void tc_gemm(const __nv_bfloat16* __restrict__ Ag, const __nv_bfloat16* __restrict__ Bg,
             void* __restrict__ Cg, void* __restrict__ Cg2,
             const float* __restrict__ bias, const float* __restrict__ bias2,
             const float* __restrict__ addend, int M, int N, int K,
             long long sA, long long sB, long long sC, long long sAdd)
{
    constexpr int S   = 3;
    constexpr int CK  = 64;                    // K elems per chunk (128B)
    constexpr int PAD = 8;
    constexpr int EPR = 8;                     // bf16 per 16B
    constexpr int LDA = TRANS_A ? (128 + PAD) : (CK + PAD);
    constexpr int LDB = 128 + PAD;
    constexpr int ASZ = (TRANS_A ? CK * (128 + PAD) : 128 * (CK + PAD)) * 2;
    constexpr int BSZ = CK * (128 + PAD) * 2;
    constexpr int STG = ASZ + BSZ;
    using AMaj = typename std::conditional<TRANS_A, wmma::col_major, wmma::row_major>::type;

    extern __shared__ __align__(16) char sm[];

    const int tid = threadIdx.x, warpId = tid >> 5, lane = tid & 31;
    const int wm = warpId >> 2, wn = warpId & 3;
    const int bn0 = blockIdx.x * 128, bm0 = blockIdx.y * 128, batch = blockIdx.z;
    const __nv_bfloat16* Ab = Ag + (long long)batch * sA;
    const __nv_bfloat16* Bb = Bg + (long long)batch * sB;

    wmma::fragment<wmma::accumulator, 16, 16, 16, float> acc[4][2];
#pragma unroll
    for (int i = 0; i < 4; i++)
#pragma unroll
        for (int j = 0; j < 2; j++) wmma::fill_fragment(acc[i][j], 0.0f);

    auto stage = [&](int k0, int slot) {
        char* At = sm + slot * STG;
        char* Bt = At + ASZ;
        if (TRANS_A) {
            constexpr int CPR = 128 / EPR;   // 16
#pragma unroll
            for (int u = 0; u < CK * CPR / 256; u++) {
                int s = tid + u * 256;
                int r = s / CPR, c = s % CPR;
                cpa16(s2u(At + (r * LDA + c * EPR) * 2),
                      Ab + (long long)(k0 + r) * M + bm0 + c * EPR);
            }
        } else {
            constexpr int CPR = CK / EPR;    // 8
#pragma unroll
            for (int u = 0; u < 128 * CPR / 256; u++) {
                int s = tid + u * 256;
                int r = s / CPR, c = s % CPR;
                cpa16(s2u(At + (r * LDA + c * EPR) * 2),
                      Ab + (long long)(bm0 + r) * K + k0 + c * EPR);
            }
        }
        {
            constexpr int CPR = 128 / EPR;   // 16
#pragma unroll
            for (int u = 0; u < CK * CPR / 256; u++) {
                int s = tid + u * 256;
                int r = s / CPR, c = s % CPR;
                cpa16(s2u(Bt + (r * LDB + c * EPR) * 2),
                      Bb + (long long)(k0 + r) * N + bn0 + c * EPR);
            }
        }
        cpa_commit();
    };

    const int NC = K / CK;
    stage(0, 0);
    if (NC > 1) stage(CK, 1);

    for (int i = 0; i < NC; i++) {
        if (i < NC - (S - 1)) cpa_wait<S - 2>();
        else                  cpa_wait<0>();
        __syncthreads();

        // prefetch BEFORE compute: keep 2 chunks in flight during the MMAs
        if (i + S - 1 < NC) stage((i + S - 1) * CK, (i + S - 1) % S);

        const __nv_bfloat16* As = (const __nv_bfloat16*)(sm + (i % S) * STG);
        const __nv_bfloat16* Bs = (const __nv_bfloat16*)(sm + (i % S) * STG + ASZ);
#pragma unroll
        for (int kk = 0; kk < CK; kk += 16) {
            wmma::fragment<wmma::matrix_a, 16, 16, 16, __nv_bfloat16, AMaj> af[4];
            wmma::fragment<wmma::matrix_b, 16, 16, 16, __nv_bfloat16, wmma::row_major> bf[2];
#pragma unroll
            for (int i2 = 0; i2 < 4; i2++) {
                const __nv_bfloat16* p = TRANS_A ? &As[kk * LDA + wm * 64 + i2 * 16]
                                                 : &As[(wm * 64 + i2 * 16) * LDA + kk];
                wmma::load_matrix_sync(af[i2], p, LDA);
            }
#pragma unroll
            for (int j = 0; j < 2; j++)
                wmma::load_matrix_sync(bf[j], &Bs[kk * LDB + wn * 32 + j * 16], LDB);
#pragma unroll
            for (int i2 = 0; i2 < 4; i2++)
#pragma unroll
                for (int j = 0; j < 2; j++)
                    wmma::mma_sync(acc[i2][j], af[i2], bf[j], acc[i2][j]);
        }
    }
    __syncthreads();

    // ---- epilogue ----
    if (EPI == 0) {
        float* Cb = (float*)Cg + (long long)batch * sC;
#pragma unroll
        for (int i = 0; i < 4; i++)
#pragma unroll
            for (int j = 0; j < 2; j++)
                wmma::store_matrix_sync(
                    Cb + (long long)(bm0 + wm * 64 + i * 16) * N + bn0 + wn * 32 + j * 16,
                    acc[i][j], N, wmma::mem_row_major);
    } else {
        float* epi = (float*)sm + warpId * 256;
        const int r  = lane >> 1;             // row within 16x16 tile
        const int c0 = (lane & 1) * 8;        // col start within tile
#pragma unroll
        for (int i = 0; i < 4; i++)
#pragma unroll
            for (int j = 0; j < 2; j++) {
                wmma::store_matrix_sync(epi, acc[i][j], 16, wmma::mem_row_major);
                __syncwarp();
                float4 v0 = ((const float4*)epi)[lane * 2];
                float4 v1 = ((const float4*)epi)[lane * 2 + 1];
                const int gm = bm0 + wm * 64 + i * 16 + r;
                const int gn = bn0 + wn * 32 + j * 16 + c0;
                if (EPI == 5) {
                    if (gm < 256) {
                        __nv_bfloat16* C = (__nv_bfloat16*)Cg + (long long)batch * sC +
                                           (long long)gm * N + gn;
                        *(uint4*)C = pack8_bf16(v0, v1, bias[gm]);
                    } else {
                        __nv_bfloat16* C = (__nv_bfloat16*)Cg2 + (long long)batch * sAdd +
                                           (long long)(gm - 256) * N + gn;
                        *(uint4*)C = pack8_bf16(v0, v1, bias2[gm - 256]);
                    }
                } else if (EPI == 2) {
                    const float bv = bias[gm];
                    const float4* X = (const float4*)(addend + (long long)batch * sAdd +
                                                      (long long)gm * N + gn);
                    float4 a0 = X[0], a1 = X[1];
                    float4 o0 = make_float4(v0.x + bv + a0.x, v0.y + bv + a0.y,
                                            v0.z + bv + a0.z, v0.w + bv + a0.w);
                    float4 o1 = make_float4(v1.x + bv + a1.x, v1.y + bv + a1.y,
                                            v1.z + bv + a1.z, v1.w + bv + a1.w);
                    float4* C = (float4*)((float*)Cg + (long long)batch * sC +
                                          (long long)gm * N + gn);
                    C[0] = o0; C[1] = o1;
                } else if (EPI == 3) {
                    __nv_bfloat16* C = (__nv_bfloat16*)Cg + (long long)batch * sC +
                                       (long long)gm * N + gn;
                    *(uint4*)C = pack8_bf16(v0, v1, bias[gm]);
                } else {  // EPI == 4
                    __nv_bfloat16* C = (__nv_bfloat16*)Cg + (long long)batch * sC +
                                       (long long)gm * N + gn;
                    *(uint4*)C = pack8_bf16(v0, v1, 0.0f);
                }
                __syncwarp();
            }
    }
}

// ============================================================================
// Row softmax over S^T rows (2048 fp32) -> normalized bf16 attn.
// ============================================================================
__global__ void softmax_rows_kernel(const float* __restrict__ S,
                                    __nv_bfloat16* __restrict__ E)
{
    const float* row = S + (size_t)blockIdx.x * 2048u;
    __nv_bfloat16* er = E + (size_t)blockIdx.x * 2048u;
    const int tid = threadIdx.x, lane = tid & 31, warp = tid >> 5;

    float4 a = reinterpret_cast<const float4*>(row)[tid];
    float4 b = reinterpret_cast<const float4*>(row)[tid + 256];

    float m = fmaxf(fmaxf(fmaxf(a.x, a.y), fmaxf(a.z, a.w)),
                    fmaxf(fmaxf(b.x, b.y), fmaxf(b.z, b.w)));
#pragma unroll
    for (int o = 16; o > 0; o >>= 1) m = fmaxf(m, __shfl_xor_sync(0xffffffffu, m, o));

    __shared__ float red[8];
    if (lane == 0) red[warp] = m;
    __syncthreads();
    float rm = red[0];
#pragma unroll
    for (int i = 1; i < 8; i++) rm = fmaxf(rm, red[i]);
    __syncthreads();

    a.x = __expf(a.x - rm); a.y = __expf(a.y - rm);
    a.z = __expf(a.z - rm); a.w = __expf(a.w - rm);
    b.x = __expf(b.x - rm); b.y = __expf(b.y - rm);
    b.z = __expf(b.z - rm); b.w = __expf(b.w - rm);

    float s = a.x + a.y + a.z + a.w + b.x + b.y + b.z + b.w;
#pragma unroll
    for (int o = 16; o > 0; o >>= 1) s += __shfl_xor_sync(0xffffffffu, s, o);
    if (lane == 0) red[warp] = s;
    __syncthreads();
    float rs = red[0];
#pragma unroll
    for (int i = 1; i < 8; i++) rs += red[i];

    float inv = 1.0f / rs;
    __nv_bfloat162 h0 = __floats2bfloat162_rn(a.x * inv, a.y * inv);
    __nv_bfloat162 h1 = __floats2bfloat162_rn(a.z * inv, a.w * inv);
    __nv_bfloat162 h2 = __floats2bfloat162_rn(b.x * inv, b.y * inv);
    __nv_bfloat162 h3 = __floats2bfloat162_rn(b.z * inv, b.w * inv);
    reinterpret_cast<uint2*>(er)[tid]       = make_uint2(*(uint32_t*)&h0, *(uint32_t*)&h1);
    reinterpret_cast<uint2*>(er)[tid + 256] = make_uint2(*(uint32_t*)&h2, *(uint32_t*)&h3);
}

// ---- weight packs (w_phi, w_mask, w_theta|w_g stacked) in ONE kernel ----
__global__ void pack_weights_kernel(const float* __restrict__ wp, const float* __restrict__ wm,
                                    const float* __restrict__ wt, const float* __restrict__ wg,
                                    __nv_bfloat16* __restrict__ Wp, __nv_bfloat16* __restrict__ Wm,
                                    __nv_bfloat16* __restrict__ Wtg)
{
    int i = blockIdx.x * blockDim.x + threadIdx.x;  // 0 .. 131071 float4 slots
    const float4* src;
    uint2* dst;
    if (i < 32768)      { src = (const float4*)wp + i;          dst = (uint2*)Wp  + i; }
    else if (i < 65536) { src = (const float4*)wm + (i - 32768); dst = (uint2*)Wm  + (i - 32768); }
    else if (i < 98304) { src = (const float4*)wt + (i - 65536); dst = (uint2*)Wtg + (i - 65536); }
    else                { src = (const float4*)wg + (i - 98304); dst = (uint2*)Wtg + (i - 65536); }
    float4 v = *src;
    __nv_bfloat162 h0 = __floats2bfloat162_rn(v.x, v.y);
    __nv_bfloat162 h1 = __floats2bfloat162_rn(v.z, v.w);
    *dst = make_uint2(*(uint32_t*)&h0, *(uint32_t*)&h1);
}

// ---- x and y -> bf16 in one kernel (blockIdx.y selects tensor) ----
__global__ void pack_xy_kernel(const float* __restrict__ x, const float* __restrict__ y,
                               __nv_bfloat16* __restrict__ Xb, __nv_bfloat16* __restrict__ Yb,
                               int n4)
{
    const float* in = blockIdx.y ? y : x;
    __nv_bfloat16* out = blockIdx.y ? Yb : Xb;
    for (int i = blockIdx.x * blockDim.x + threadIdx.x; i < n4; i += gridDim.x * blockDim.x) {
        float4 v = reinterpret_cast<const float4*>(in)[i];
        __nv_bfloat162 h0 = __floats2bfloat162_rn(v.x, v.y);
        __nv_bfloat162 h1 = __floats2bfloat162_rn(v.z, v.w);
        reinterpret_cast<uint2*>(out)[i] = make_uint2(*(uint32_t*)&h0, *(uint32_t*)&h1);
    }
}

// ============================================================================
extern "C" void kernel_launch(void* const* d_in, const int* in_sizes, int n_in,
                              void* d_out, int out_size)
{
    const float* x       = (const float*)d_in[0];
    const float* y       = (const float*)d_in[1];
    const float* w_phi   = (const float*)d_in[2];
    const float* b_phi   = (const float*)d_in[3];
    const float* w_theta = (const float*)d_in[4];
    const float* b_theta = (const float*)d_in[5];
    const float* w_g     = (const float*)d_in[6];
    const float* b_g     = (const float*)d_in[7];
    const float* w_mask  = (const float*)d_in[8];
    const float* b_mask  = (const float*)d_in[9];
    float* out = (float*)d_out;

    float* S;
    __nv_bfloat16 *Xb, *Yb, *P, *T, *Gb, *Eb, *Ob, *Wtg, *Wp, *Wm;
    cudaGetSymbolAddress((void**)&Xb, g_Xb);
    cudaGetSymbolAddress((void**)&Yb, g_Yb);
    cudaGetSymbolAddress((void**)&P,  g_P);
    cudaGetSymbolAddress((void**)&T,  g_T);
    cudaGetSymbolAddress((void**)&Gb, g_Gb);
    cudaGetSymbolAddress((void**)&S,  g_S);
    cudaGetSymbolAddress((void**)&Eb, g_Eb);
    cudaGetSymbolAddress((void**)&Ob, g_Ob);
    cudaGetSymbolAddress((void**)&Wtg, g_Wtg);
    cudaGetSymbolAddress((void**)&Wp, g_Wp);
    cudaGetSymbolAddress((void**)&Wm, g_Wm);

    const int smN = 3 * (128 * 72 + 64 * 136) * 2;  // 107520
    const int smT = 3 * (2 * 64 * 136) * 2;         // 104448

    cudaFuncSetAttribute((const void*)tc_gemm<false, 3>,
                         cudaFuncAttributeMaxDynamicSharedMemorySize, smN);
    cudaFuncSetAttribute((const void*)tc_gemm<false, 5>,
                         cudaFuncAttributeMaxDynamicSharedMemorySize, smN);
    cudaFuncSetAttribute((const void*)tc_gemm<true, 0>,
                         cudaFuncAttributeMaxDynamicSharedMemorySize, smT);
    cudaFuncSetAttribute((const void*)tc_gemm<false, 4>,
                         cudaFuncAttributeMaxDynamicSharedMemorySize, smN);
    cudaFuncSetAttribute((const void*)tc_gemm<false, 2>,
                         cudaFuncAttributeMaxDynamicSharedMemorySize, smN);

    const dim3 blk(256);
    const long long sImg  = 512LL * 4096;   // fp32 x/y per-batch stride (elements)
    const long long sHalf = 256LL * 4096;   // conv-out per-batch stride
    const long long sS    = 2048LL * 2048;

    // packs
    pack_weights_kernel<<<512, 256>>>(w_phi, w_mask, w_theta, w_g, Wp, Wm, Wtg);
    pack_xy_kernel<<<dim3(2048, 2), 256>>>(x, y, Xb, Yb, (int)(8 * sImg / 4));

    // phi conv: Wp[256,512] x Yb[512,4096] + b_phi -> P bf16
    tc_gemm<false, 3><<<dim3(32, 2, 8), blk, smN>>>(
        Wp, Yb, P, nullptr, b_phi, nullptr, nullptr,
        256, 4096, 512, 0, sImg, sHalf, 0);

    // merged theta+g conv: Wtg[512,512] x Xb; rows<256 -> T (+b_theta), rows>=256 -> Gb (+b_g)
    tc_gemm<false, 5><<<dim3(32, 4, 8), blk, smN>>>(
        Wtg, Xb, T, Gb, b_theta, b_g, nullptr,
        512, 4096, 512, 0, sImg, sHalf, sHalf);

    // S^T[m,n] = sum_c P_v[c,m] * T_v[c,n]  (A trans [512,2048], fp32 out)
    tc_gemm<true, 0><<<dim3(16, 16, 8), blk, smT>>>(
        P, T, S, nullptr, nullptr, nullptr, nullptr,
        2048, 2048, 512, sHalf, sHalf, sS, 0);

    // softmax rows of S^T -> normalized bf16 attn
    softmax_rows_kernel<<<8 * 2048, 256>>>(S, Eb);

    // Out_v = g_v[512,2048] @ E[2048,2048] -> Ob bf16
    tc_gemm<false, 4><<<dim3(16, 4, 8), blk, smN>>>(
        Gb, Eb, Ob, nullptr, nullptr, nullptr, nullptr,
        512, 2048, 2048, sHalf, sS, sHalf, 0);

    // out = Wm[512,256] @ Ob(view [256,4096]) + b_mask + x  (fp32 out)
    tc_gemm<false, 2><<<dim3(32, 4, 8), blk, smN>>>(
        Wm, Ob, out, nullptr, b_mask, nullptr, x,
        512, 4096, 256, 0, sHalf, sImg, sImg);
}

// round 16
// speedup vs baseline: 3.2466x; 1.0859x over previous
#include <cuda_runtime.h>
#include <cuda_bf16.h>
#include <mma.h>
#include <cstdint>
#include <type_traits>

using namespace nvcuda;

// ---- scratch (__device__ globals; no allocations allowed) ----
__device__ __align__(16) __nv_bfloat16 g_Xb[8u * 2097152u];   // x bf16 [512,4096]/b
__device__ __align__(16) __nv_bfloat16 g_Yb[8u * 2097152u];   // y bf16
__device__ __align__(16) __nv_bfloat16 g_P[8u * 1048576u];    // phi conv out bf16 (viewed [512,2048]/b)
__device__ __align__(16) __nv_bfloat16 g_T[8u * 1048576u];    // theta conv out bf16
__device__ __align__(16) __nv_bfloat16 g_Gb[8u * 1048576u];   // g conv out bf16
__device__ __align__(16) float         g_S[8u * 4194304u];    // S^T fp32 scores
__device__ __align__(16) __nv_bfloat16 g_Eb[8u * 4194304u];   // normalized attn bf16
__device__ __align__(16) __nv_bfloat16 g_Ob[8u * 1048576u];   // O out bf16 (viewed [256,4096]/b)
__device__ __align__(16) __nv_bfloat16 g_Wtg[262144u];        // [w_theta; w_g] bf16
__device__ __align__(16) __nv_bfloat16 g_Wp[131072u];         // w_phi bf16
__device__ __align__(16) __nv_bfloat16 g_Wm[131072u];         // w_mask bf16

// ---- helpers ----
static __device__ __forceinline__ uint32_t s2u(const void* p) {
    uint32_t a;
    asm("{ .reg .u64 t; cvta.to.shared.u64 t, %1; cvt.u32.u64 %0, t; }" : "=r"(a) : "l"(p));
    return a;
}
static __device__ __forceinline__ void cpa16(uint32_t s, const void* g) {
    asm volatile("cp.async.cg.shared.global [%0], [%1], 16;" :: "r"(s), "l"(g));
}
static __device__ __forceinline__ void cpa_commit() {
    asm volatile("cp.async.commit_group;" ::: "memory");
}
template <int N>
static __device__ __forceinline__ void cpa_wait() {
    asm volatile("cp.async.wait_group %0;" :: "n"(N) : "memory");
}
static __device__ __forceinline__ uint4 pack8_bf16(float4 v0, float4 v1, float add) {
    uint4 o;
    __nv_bfloat162 h;
    h = __floats2bfloat162_rn(v0.x + add, v0.y + add); o.x = *(uint32_t*)&h;
    h = __floats2bfloat162_rn(v0.z + add, v0.w + add); o.y = *(uint32_t*)&h;
    h = __floats2bfloat162_rn(v1.x + add, v1.y + add); o.z = *(uint32_t*)&h;
    h = __floats2bfloat162_rn(v1.z + add, v1.w + add); o.w = *(uint32_t*)&h;
    return o;
}

// ============================================================================
// 3-stage cp.async bf16 GEMM, 128x128 CTA tile, 128 thr, 4 warps, 64x64 warp tile.
//   A: TRANS_A ? [K,M] (lda=M) : [M,K] (lda=K);  B: [K,N] row-major. bf16.
//   EPI: 0 fp32 plain | 2 fp32+bias[gm]+addend | 3 bf16+bias[gm] | 4 bf16 plain
//        5 split: gm<256 -> bf16 Cg +bias; gm>=256 -> bf16 Cg2 +bias2[gm-256]
// ============================================================================
template <bool TRANS_A, int EPI>
__global__ __launch_bounds__(128, 2)
void tc_gemm(const __nv_bfloat16* __restrict__ Ag, const __nv_bfloat16* __restrict__ Bg,
             void* __restrict__ Cg, void* __restrict__ Cg2,
             const float* __restrict__ bias, const float* __restrict__ bias2,
             const float* __restrict__ addend, int M, int N, int K,
             long long sA, long long sB, long long sC, long long sAdd)
{
    constexpr int S   = 3;
    constexpr int CK  = 64;                    // K elems per chunk (128B)
    constexpr int PAD = 8;
    constexpr int EPR = 8;                     // bf16 per 16B
    constexpr int LDA = TRANS_A ? (128 + PAD) : (CK + PAD);
    constexpr int LDB = 128 + PAD;
    constexpr int ASZ = (TRANS_A ? CK * (128 + PAD) : 128 * (CK + PAD)) * 2;
    constexpr int BSZ = CK * (128 + PAD) * 2;
    constexpr int STG = ASZ + BSZ;
    using AMaj = typename std::conditional<TRANS_A, wmma::col_major, wmma::row_major>::type;

    extern __shared__ __align__(16) char sm[];

    const int tid = threadIdx.x, warpId = tid >> 5, lane = tid & 31;
    const int wm = warpId >> 1, wn = warpId & 1;          // 2x2 warps, 64x64 each
    const int bn0 = blockIdx.x * 128, bm0 = blockIdx.y * 128, batch = blockIdx.z;
    const __nv_bfloat16* Ab = Ag + (long long)batch * sA;
    const __nv_bfloat16* Bb = Bg + (long long)batch * sB;

    wmma::fragment<wmma::accumulator, 16, 16, 16, float> acc[4][4];
#pragma unroll
    for (int i = 0; i < 4; i++)
#pragma unroll
        for (int j = 0; j < 4; j++) wmma::fill_fragment(acc[i][j], 0.0f);

    auto stage = [&](int k0, int slot) {
        char* At = sm + slot * STG;
        char* Bt = At + ASZ;
        if (TRANS_A) {
            constexpr int CPR = 128 / EPR;   // 16 vecs per row of CKx128
#pragma unroll
            for (int u = 0; u < CK * CPR / 128; u++) {   // 8
                int s = tid + u * 128;
                int r = s / CPR, c = s % CPR;
                cpa16(s2u(At + (r * LDA + c * EPR) * 2),
                      Ab + (long long)(k0 + r) * M + bm0 + c * EPR);
            }
        } else {
            constexpr int CPR = CK / EPR;    // 8 vecs per row of 128xCK
#pragma unroll
            for (int u = 0; u < 128 * CPR / 128; u++) {  // 8
                int s = tid + u * 128;
                int r = s / CPR, c = s % CPR;
                cpa16(s2u(At + (r * LDA + c * EPR) * 2),
                      Ab + (long long)(bm0 + r) * K + k0 + c * EPR);
            }
        }
        {
            constexpr int CPR = 128 / EPR;   // 16
#pragma unroll
            for (int u = 0; u < CK * CPR / 128; u++) {   // 8
                int s = tid + u * 128;
                int r = s / CPR, c = s % CPR;
                cpa16(s2u(Bt + (r * LDB + c * EPR) * 2),
                      Bb + (long long)(k0 + r) * N + bn0 + c * EPR);
            }
        }
        cpa_commit();
    };

    const int NC = K / CK;
    stage(0, 0);
    if (NC > 1) stage(CK, 1);

    for (int i = 0; i < NC; i++) {
        if (i < NC - (S - 1)) cpa_wait<S - 2>();
        else                  cpa_wait<0>();
        __syncthreads();

        // prefetch BEFORE compute: keep 2 chunks in flight during the MMAs
        if (i + S - 1 < NC) stage((i + S - 1) * CK, (i + S - 1) % S);

        const __nv_bfloat16* As = (const __nv_bfloat16*)(sm + (i % S) * STG);
        const __nv_bfloat16* Bs = (const __nv_bfloat16*)(sm + (i % S) * STG + ASZ);
#pragma unroll
        for (int kk = 0; kk < CK; kk += 16) {
            wmma::fragment<wmma::matrix_a, 16, 16, 16, __nv_bfloat16, AMaj> af[4];
            wmma::fragment<wmma::matrix_b, 16, 16, 16, __nv_bfloat16, wmma::row_major> bf[4];
#pragma unroll
            for (int i2 = 0; i2 < 4; i2++) {
                const __nv_bfloat16* p = TRANS_A ? &As[kk * LDA + wm * 64 + i2 * 16]
                                                 : &As[(wm * 64 + i2 * 16) * LDA + kk];
                wmma::load_matrix_sync(af[i2], p, LDA);
            }
#pragma unroll
            for (int j = 0; j < 4; j++)
                wmma::load_matrix_sync(bf[j], &Bs[kk * LDB + wn * 64 + j * 16], LDB);
#pragma unroll
            for (int i2 = 0; i2 < 4; i2++)
#pragma unroll
                for (int j = 0; j < 4; j++)
                    wmma::mma_sync(acc[i2][j], af[i2], bf[j], acc[i2][j]);
        }
    }
    __syncthreads();

    // ---- epilogue ----
    if (EPI == 0) {
        float* Cb = (float*)Cg + (long long)batch * sC;
#pragma unroll
        for (int i = 0; i < 4; i++)
#pragma unroll
            for (int j = 0; j < 4; j++)
                wmma::store_matrix_sync(
                    Cb + (long long)(bm0 + wm * 64 + i * 16) * N + bn0 + wn * 64 + j * 16,
                    acc[i][j], N, wmma::mem_row_major);
    } else {
        float* epi = (float*)sm + warpId * 256;
        const int r  = lane >> 1;             // row within 16x16 tile
        const int c0 = (lane & 1) * 8;        // col start within tile
#pragma unroll
        for (int i = 0; i < 4; i++)
#pragma unroll
            for (int j = 0; j < 4; j++) {
                wmma::store_matrix_sync(epi, acc[i][j], 16, wmma::mem_row_major);
                __syncwarp();
                float4 v0 = ((const float4*)epi)[lane * 2];
                float4 v1 = ((const float4*)epi)[lane * 2 + 1];
                const int gm = bm0 + wm * 64 + i * 16 + r;
                const int gn = bn0 + wn * 64 + j * 16 + c0;
                if (EPI == 5) {
                    if (gm < 256) {
                        __nv_bfloat16* C = (__nv_bfloat16*)Cg + (long long)batch * sC +
                                           (long long)gm * N + gn;
                        *(uint4*)C = pack8_bf16(v0, v1, bias[gm]);
                    } else {
                        __nv_bfloat16* C = (__nv_bfloat16*)Cg2 + (long long)batch * sAdd +
                                           (long long)(gm - 256) * N + gn;
                        *(uint4*)C = pack8_bf16(v0, v1, bias2[gm - 256]);
                    }
                } else if (EPI == 2) {
                    const float bv = bias[gm];
                    const float4* X = (const float4*)(addend + (long long)batch * sAdd +
                                                      (long long)gm * N + gn);
                    float4 a0 = X[0], a1 = X[1];
                    float4 o0 = make_float4(v0.x + bv + a0.x, v0.y + bv + a0.y,
                                            v0.z + bv + a0.z, v0.w + bv + a0.w);
                    float4 o1 = make_float4(v1.x + bv + a1.x, v1.y + bv + a1.y,
                                            v1.z + bv + a1.z, v1.w + bv + a1.w);
                    float4* C = (float4*)((float*)Cg + (long long)batch * sC +
                                          (long long)gm * N + gn);
                    C[0] = o0; C[1] = o1;
                } else if (EPI == 3) {
                    __nv_bfloat16* C = (__nv_bfloat16*)Cg + (long long)batch * sC +
                                       (long long)gm * N + gn;
                    *(uint4*)C = pack8_bf16(v0, v1, bias[gm]);
                } else {  // EPI == 4
                    __nv_bfloat16* C = (__nv_bfloat16*)Cg + (long long)batch * sC +
                                       (long long)gm * N + gn;
                    *(uint4*)C = pack8_bf16(v0, v1, 0.0f);
                }
                __syncwarp();
            }
    }
}

// ============================================================================
// Row softmax over S^T rows (2048 fp32) -> normalized bf16 attn.
// ============================================================================
__global__ void softmax_rows_kernel(const float* __restrict__ S,
                                    __nv_bfloat16* __restrict__ E)
{
    const float* row = S + (size_t)blockIdx.x * 2048u;
    __nv_bfloat16* er = E + (size_t)blockIdx.x * 2048u;
    const int tid = threadIdx.x, lane = tid & 31, warp = tid >> 5;

    float4 a = reinterpret_cast<const float4*>(row)[tid];
    float4 b = reinterpret_cast<const float4*>(row)[tid + 256];

    float m = fmaxf(fmaxf(fmaxf(a.x, a.y), fmaxf(a.z, a.w)),
                    fmaxf(fmaxf(b.x, b.y), fmaxf(b.z, b.w)));
#pragma unroll
    for (int o = 16; o > 0; o >>= 1) m = fmaxf(m, __shfl_xor_sync(0xffffffffu, m, o));

    __shared__ float red[8];
    if (lane == 0) red[warp] = m;
    __syncthreads();
    float rm = red[0];
#pragma unroll
    for (int i = 1; i < 8; i++) rm = fmaxf(rm, red[i]);
    __syncthreads();

    a.x = __expf(a.x - rm); a.y = __expf(a.y - rm);
    a.z = __expf(a.z - rm); a.w = __expf(a.w - rm);
    b.x = __expf(b.x - rm); b.y = __expf(b.y - rm);
    b.z = __expf(b.z - rm); b.w = __expf(b.w - rm);

    float s = a.x + a.y + a.z + a.w + b.x + b.y + b.z + b.w;
#pragma unroll
    for (int o = 16; o > 0; o >>= 1) s += __shfl_xor_sync(0xffffffffu, s, o);
    if (lane == 0) red[warp] = s;
    __syncthreads();
    float rs = red[0];
#pragma unroll
    for (int i = 1; i < 8; i++) rs += red[i];

    float inv = 1.0f / rs;
    __nv_bfloat162 h0 = __floats2bfloat162_rn(a.x * inv, a.y * inv);
    __nv_bfloat162 h1 = __floats2bfloat162_rn(a.z * inv, a.w * inv);
    __nv_bfloat162 h2 = __floats2bfloat162_rn(b.x * inv, b.y * inv);
    __nv_bfloat162 h3 = __floats2bfloat162_rn(b.z * inv, b.w * inv);
    reinterpret_cast<uint2*>(er)[tid]       = make_uint2(*(uint32_t*)&h0, *(uint32_t*)&h1);
    reinterpret_cast<uint2*>(er)[tid + 256] = make_uint2(*(uint32_t*)&h2, *(uint32_t*)&h3);
}

// ---- weight packs (w_phi, w_mask, w_theta|w_g stacked) in ONE kernel ----
__global__ void pack_weights_kernel(const float* __restrict__ wp, const float* __restrict__ wm,
                                    const float* __restrict__ wt, const float* __restrict__ wg,
                                    __nv_bfloat16* __restrict__ Wp, __nv_bfloat16* __restrict__ Wm,
                                    __nv_bfloat16* __restrict__ Wtg)
{
    int i = blockIdx.x * blockDim.x + threadIdx.x;  // 0 .. 131071 float4 slots
    const float4* src;
    uint2* dst;
    if (i < 32768)      { src = (const float4*)wp + i;          dst = (uint2*)Wp  + i; }
    else if (i < 65536) { src = (const float4*)wm + (i - 32768); dst = (uint2*)Wm  + (i - 32768); }
    else if (i < 98304) { src = (const float4*)wt + (i - 65536); dst = (uint2*)Wtg + (i - 65536); }
    else                { src = (const float4*)wg + (i - 98304); dst = (uint2*)Wtg + (i - 65536); }
    float4 v = *src;
    __nv_bfloat162 h0 = __floats2bfloat162_rn(v.x, v.y);
    __nv_bfloat162 h1 = __floats2bfloat162_rn(v.z, v.w);
    *dst = make_uint2(*(uint32_t*)&h0, *(uint32_t*)&h1);
}

// ---- x and y -> bf16 in one kernel (blockIdx.y selects tensor) ----
__global__ void pack_xy_kernel(const float* __restrict__ x, const float* __restrict__ y,
                               __nv_bfloat16* __restrict__ Xb, __nv_bfloat16* __restrict__ Yb,
                               int n4)
{
    const float* in = blockIdx.y ? y : x;
    __nv_bfloat16* out = blockIdx.y ? Yb : Xb;
    for (int i = blockIdx.x * blockDim.x + threadIdx.x; i < n4; i += gridDim.x * blockDim.x) {
        float4 v = reinterpret_cast<const float4*>(in)[i];
        __nv_bfloat162 h0 = __floats2bfloat162_rn(v.x, v.y);
        __nv_bfloat162 h1 = __floats2bfloat162_rn(v.z, v.w);
        reinterpret_cast<uint2*>(out)[i] = make_uint2(*(uint32_t*)&h0, *(uint32_t*)&h1);
    }
}

// ============================================================================
extern "C" void kernel_launch(void* const* d_in, const int* in_sizes, int n_in,
                              void* d_out, int out_size)
{
    const float* x       = (const float*)d_in[0];
    const float* y       = (const float*)d_in[1];
    const float* w_phi   = (const float*)d_in[2];
    const float* b_phi   = (const float*)d_in[3];
    const float* w_theta = (const float*)d_in[4];
    const float* b_theta = (const float*)d_in[5];
    const float* w_g     = (const float*)d_in[6];
    const float* b_g     = (const float*)d_in[7];
    const float* w_mask  = (const float*)d_in[8];
    const float* b_mask  = (const float*)d_in[9];
    float* out = (float*)d_out;

    float* S;
    __nv_bfloat16 *Xb, *Yb, *P, *T, *Gb, *Eb, *Ob, *Wtg, *Wp, *Wm;
    cudaGetSymbolAddress((void**)&Xb, g_Xb);
    cudaGetSymbolAddress((void**)&Yb, g_Yb);
    cudaGetSymbolAddress((void**)&P,  g_P);
    cudaGetSymbolAddress((void**)&T,  g_T);
    cudaGetSymbolAddress((void**)&Gb, g_Gb);
    cudaGetSymbolAddress((void**)&S,  g_S);
    cudaGetSymbolAddress((void**)&Eb, g_Eb);
    cudaGetSymbolAddress((void**)&Ob, g_Ob);
    cudaGetSymbolAddress((void**)&Wtg, g_Wtg);
    cudaGetSymbolAddress((void**)&Wp, g_Wp);
    cudaGetSymbolAddress((void**)&Wm, g_Wm);

    const int smN = 3 * (128 * 72 + 64 * 136) * 2;  // 107520
    const int smT = 3 * (2 * 64 * 136) * 2;         // 104448

    cudaFuncSetAttribute((const void*)tc_gemm<false, 3>,
                         cudaFuncAttributeMaxDynamicSharedMemorySize, smN);
    cudaFuncSetAttribute((const void*)tc_gemm<false, 5>,
                         cudaFuncAttributeMaxDynamicSharedMemorySize, smN);
    cudaFuncSetAttribute((const void*)tc_gemm<true, 0>,
                         cudaFuncAttributeMaxDynamicSharedMemorySize, smT);
    cudaFuncSetAttribute((const void*)tc_gemm<false, 4>,
                         cudaFuncAttributeMaxDynamicSharedMemorySize, smN);
    cudaFuncSetAttribute((const void*)tc_gemm<false, 2>,
                         cudaFuncAttributeMaxDynamicSharedMemorySize, smN);

    const dim3 blk(128);
    const long long sImg  = 512LL * 4096;   // fp32 x/y per-batch stride (elements)
    const long long sHalf = 256LL * 4096;   // conv-out per-batch stride
    const long long sS    = 2048LL * 2048;

    // packs
    pack_weights_kernel<<<512, 256>>>(w_phi, w_mask, w_theta, w_g, Wp, Wm, Wtg);
    pack_xy_kernel<<<dim3(2048, 2), 256>>>(x, y, Xb, Yb, (int)(8 * sImg / 4));

    // phi conv: Wp[256,512] x Yb[512,4096] + b_phi -> P bf16
    tc_gemm<false, 3><<<dim3(32, 2, 8), blk, smN>>>(
        Wp, Yb, P, nullptr, b_phi, nullptr, nullptr,
        256, 4096, 512, 0, sImg, sHalf, 0);

    // merged theta+g conv: Wtg[512,512] x Xb; rows<256 -> T (+b_theta), rows>=256 -> Gb (+b_g)
    tc_gemm<false, 5><<<dim3(32, 4, 8), blk, smN>>>(
        Wtg, Xb, T, Gb, b_theta, b_g, nullptr,
        512, 4096, 512, 0, sImg, sHalf, sHalf);

    // S^T[m,n] = sum_c P_v[c,m] * T_v[c,n]  (A trans [512,2048], fp32 out)
    tc_gemm<true, 0><<<dim3(16, 16, 8), blk, smT>>>(
        P, T, S, nullptr, nullptr, nullptr, nullptr,
        2048, 2048, 512, sHalf, sHalf, sS, 0);

    // softmax rows of S^T -> normalized bf16 attn
    softmax_rows_kernel<<<8 * 2048, 256>>>(S, Eb);

    // Out_v = g_v[512,2048] @ E[2048,2048] -> Ob bf16
    tc_gemm<false, 4><<<dim3(16, 4, 8), blk, smN>>>(
        Gb, Eb, Ob, nullptr, nullptr, nullptr, nullptr,
        512, 2048, 2048, sHalf, sS, sHalf, 0);

    // out = Wm[512,256] @ Ob(view [256,4096]) + b_mask + x  (fp32 out)
    tc_gemm<false, 2><<<dim3(32, 4, 8), blk, smN>>>(
        Wm, Ob, out, nullptr, b_mask, nullptr, x,
        512, 4096, 256, 0, sHalf, sImg, sImg);
}